// round 6
// baseline (speedup 1.0000x reference)
#include <cuda_runtime.h>
#include <cuda_bf16.h>
#include <cstdint>

// Problem constants
#define BB   2
#define LL   2048
#define SS   2048
#define DIN  512
#define DK   512
#define DV   512
#define DOUT 512
#define HH   8
#define HD   64

#define OUT_ELEMS  ((long)BB * LL * DOUT)
#define PROB_ELEMS ((long)BB * HH * (long)LL * (long)SS)

// Scratch (device globals — no runtime allocation allowed)
__device__ float g_q  [BB * LL * DK];
__device__ float g_k  [BB * SS * DK];
__device__ float g_v  [BB * SS * DV];
__device__ float g_cb [BB * HH * SS];
__device__ float g_ctx[BB * LL * DV];
__device__ float g_psum[BB * HH * (long)LL * 16];   // per-(row, s-tile) partial expsums
__device__ float g_probs[BB * HH * (long)LL * SS];

// ---------------------------------------------------------------------------
// tf32 helpers (harness targets plain sm_103 — no tcgen05; mma.sync is the
// tensor path)
// ---------------------------------------------------------------------------
__device__ __forceinline__ float f2tf32(float v) {
    uint32_t r;
    asm("cvt.rna.tf32.f32 %0, %1;" : "=r"(r) : "f"(v));
    return __uint_as_float(r);
}

__device__ __forceinline__ void mma_tf32(float& c0, float& c1, float& c2, float& c3,
                                         float a0, float a1, float a2, float a3,
                                         float b0, float b1) {
    asm volatile(
        "mma.sync.aligned.m16n8k8.row.col.f32.tf32.tf32.f32 "
        "{%0,%1,%2,%3}, {%4,%5,%6,%7}, {%8,%9}, {%0,%1,%2,%3};"
        : "+f"(c0), "+f"(c1), "+f"(c2), "+f"(c3)
        : "r"(__float_as_uint(a0)), "r"(__float_as_uint(a1)),
          "r"(__float_as_uint(a2)), "r"(__float_as_uint(a3)),
          "r"(__float_as_uint(b0)), "r"(__float_as_uint(b1)));
}

#define SKP 20   // smem row stride (floats): conflict-free fragment reads

// ---------------------------------------------------------------------------
// Generic tf32 mma GEMM: C[M,N] = A[M,K] * W[N,K]^T (+ bias[n])
// ---------------------------------------------------------------------------
template <bool HAS_BIAS>
__global__ __launch_bounds__(256, 2)
void gemm_mma_kernel(const float* __restrict__ A,
                     const float* __restrict__ W,
                     const float* __restrict__ bias,
                     float* __restrict__ C,
                     int M, int N, int K) {
    __shared__ float As[2][128][SKP];
    __shared__ float Bs[2][128][SKP];
    __shared__ float bias_s[128];

    const int tid  = threadIdx.x;
    const int wid  = tid >> 5;
    const int lane = tid & 31;
    const int warp_m = wid >> 2;
    const int warp_n = wid & 3;

    const int bm = blockIdx.y * 128;
    const int bn = blockIdx.x * 128;

    const float* Ag = A + (size_t)bm * K;
    const float* Wg = W + (size_t)bn * K;

    if (HAS_BIAS && tid < 128) bias_s[tid] = bias[bn + tid];
    __syncthreads();

    const int gr = tid >> 2;
    const int gc = (tid & 3) * 4;

    float acc[4][4][4];
    #pragma unroll
    for (int i = 0; i < 4; i++)
        #pragma unroll
        for (int j = 0; j < 4; j++)
            #pragma unroll
            for (int t = 0; t < 4; t++) acc[i][j][t] = 0.0f;

    float4 pa[2], pb[2];

    #pragma unroll
    for (int i = 0; i < 2; i++) {
        pa[i] = *(const float4*)(Ag + (size_t)(gr + i * 64) * K + gc);
        pb[i] = *(const float4*)(Wg + (size_t)(gr + i * 64) * K + gc);
    }
    #pragma unroll
    for (int i = 0; i < 2; i++) {
        int r = gr + i * 64;
        float4 ta = make_float4(f2tf32(pa[i].x), f2tf32(pa[i].y), f2tf32(pa[i].z), f2tf32(pa[i].w));
        float4 tb = make_float4(f2tf32(pb[i].x), f2tf32(pb[i].y), f2tf32(pb[i].z), f2tf32(pb[i].w));
        *(float4*)&As[0][r][gc] = ta;
        *(float4*)&Bs[0][r][gc] = tb;
    }
    __syncthreads();

    const int NC = K / 16;
    for (int c = 0; c < NC; c++) {
        if (c + 1 < NC) {
            int kc = (c + 1) * 16;
            #pragma unroll
            for (int i = 0; i < 2; i++) {
                pa[i] = *(const float4*)(Ag + (size_t)(gr + i * 64) * K + kc + gc);
                pb[i] = *(const float4*)(Wg + (size_t)(gr + i * 64) * K + kc + gc);
            }
        }

        const int st = c & 1;
        #pragma unroll
        for (int kk = 0; kk < 2; kk++) {
            const int k0 = kk * 8;
            const int ar = lane >> 2;
            const int ac = lane & 3;
            float a0[4], a1[4], a2[4], a3[4];
            #pragma unroll
            for (int i = 0; i < 4; i++) {
                int m = warp_m * 64 + i * 16;
                a0[i] = As[st][m + ar    ][k0 + ac    ];
                a1[i] = As[st][m + ar + 8][k0 + ac    ];
                a2[i] = As[st][m + ar    ][k0 + ac + 4];
                a3[i] = As[st][m + ar + 8][k0 + ac + 4];
            }
            float b0[4], b1[4];
            #pragma unroll
            for (int j = 0; j < 4; j++) {
                int n = warp_n * 32 + j * 8 + (lane >> 2);
                b0[j] = Bs[st][n][k0 + ac    ];
                b1[j] = Bs[st][n][k0 + ac + 4];
            }
            #pragma unroll
            for (int i = 0; i < 4; i++)
                #pragma unroll
                for (int j = 0; j < 4; j++)
                    mma_tf32(acc[i][j][0], acc[i][j][1], acc[i][j][2], acc[i][j][3],
                             a0[i], a1[i], a2[i], a3[i], b0[j], b1[j]);
        }

        if (c + 1 < NC) {
            __syncthreads();
            const int ns = (c + 1) & 1;
            #pragma unroll
            for (int i = 0; i < 2; i++) {
                int r = gr + i * 64;
                float4 ta = make_float4(f2tf32(pa[i].x), f2tf32(pa[i].y), f2tf32(pa[i].z), f2tf32(pa[i].w));
                float4 tb = make_float4(f2tf32(pb[i].x), f2tf32(pb[i].y), f2tf32(pb[i].z), f2tf32(pb[i].w));
                *(float4*)&As[ns][r][gc] = ta;
                *(float4*)&Bs[ns][r][gc] = tb;
            }
            __syncthreads();
        }
    }

    #pragma unroll
    for (int i = 0; i < 4; i++) {
        int row = bm + warp_m * 64 + i * 16 + (lane >> 2);
        #pragma unroll
        for (int j = 0; j < 4; j++) {
            int col = warp_n * 32 + j * 8 + (lane & 3) * 2;
            float bb0 = HAS_BIAS ? bias_s[col]     : 0.0f;
            float bb1 = HAS_BIAS ? bias_s[col + 1] : 0.0f;
            float2 v0, v1;
            v0.x = acc[i][j][0] + bb0; v0.y = acc[i][j][1] + bb1;
            v1.x = acc[i][j][2] + bb0; v1.y = acc[i][j][3] + bb1;
            *(float2*)(C + (size_t)row * N + bn + col) = v0;
            *(float2*)(C + (size_t)(row + 8) * N + bn + col) = v1;
        }
    }
}

// ---------------------------------------------------------------------------
// Scores via tf32 mma, fused exp + partial row sums:
//   e[b,h,l,s] = exp((sum_e q*mix*k + cb) / 8)     -> probs buffer
//   psum[z,l,cta_n] = sum of e over this CTA's 128 s-columns (deterministic)
// ---------------------------------------------------------------------------
__global__ __launch_bounds__(256, 2)
void scores_mma_kernel(const float* __restrict__ q,
                       const float* __restrict__ kmat,
                       const float* __restrict__ mixing,
                       const float* __restrict__ cb,
                       float* __restrict__ probs,
                       float* __restrict__ psum) {
    __shared__ float As[2][128][SKP];
    __shared__ float Bs[2][128][SKP];
    __shared__ float mix_s[DK];
    __shared__ float cb_s[128];
    __shared__ float rs[4][130];

    const int tid  = threadIdx.x;
    const int wid  = tid >> 5;
    const int lane = tid & 31;
    const int warp_m = wid >> 2;
    const int warp_n = wid & 3;

    const int z  = blockIdx.z;
    const int b  = z >> 3;
    const int h  = z & 7;
    const int bm = blockIdx.y * 128;
    const int bn = blockIdx.x * 128;

    const float* Aq = q    + (size_t)b * LL * DK + (size_t)bm * DK;
    const float* Bk = kmat + (size_t)b * SS * DK + (size_t)bn * DK;

    for (int i = tid; i < DK; i += 256) mix_s[i] = mixing[h * DK + i];
    if (tid < 128) cb_s[tid] = cb[(size_t)(b * HH + h) * SS + bn + tid];
    __syncthreads();

    const int gr = tid >> 2;
    const int gc = (tid & 3) * 4;

    float acc[4][4][4];
    #pragma unroll
    for (int i = 0; i < 4; i++)
        #pragma unroll
        for (int j = 0; j < 4; j++)
            #pragma unroll
            for (int t = 0; t < 4; t++) acc[i][j][t] = 0.0f;

    float4 pa[2], pb[2];

    #pragma unroll
    for (int i = 0; i < 2; i++) {
        pa[i] = *(const float4*)(Aq + (size_t)(gr + i * 64) * DK + gc);
        pb[i] = *(const float4*)(Bk + (size_t)(gr + i * 64) * DK + gc);
    }
    #pragma unroll
    for (int i = 0; i < 2; i++) {
        int r = gr + i * 64;
        As[0][r][gc + 0] = f2tf32(pa[i].x);
        As[0][r][gc + 1] = f2tf32(pa[i].y);
        As[0][r][gc + 2] = f2tf32(pa[i].z);
        As[0][r][gc + 3] = f2tf32(pa[i].w);
        Bs[0][r][gc + 0] = f2tf32(pb[i].x * mix_s[gc + 0]);
        Bs[0][r][gc + 1] = f2tf32(pb[i].y * mix_s[gc + 1]);
        Bs[0][r][gc + 2] = f2tf32(pb[i].z * mix_s[gc + 2]);
        Bs[0][r][gc + 3] = f2tf32(pb[i].w * mix_s[gc + 3]);
    }
    __syncthreads();

    const int NC = DK / 16;
    for (int c = 0; c < NC; c++) {
        if (c + 1 < NC) {
            int kc = (c + 1) * 16;
            #pragma unroll
            for (int i = 0; i < 2; i++) {
                pa[i] = *(const float4*)(Aq + (size_t)(gr + i * 64) * DK + kc + gc);
                pb[i] = *(const float4*)(Bk + (size_t)(gr + i * 64) * DK + kc + gc);
            }
        }

        const int st = c & 1;
        #pragma unroll
        for (int kk = 0; kk < 2; kk++) {
            const int k0 = kk * 8;
            const int ar = lane >> 2;
            const int ac = lane & 3;
            float a0[4], a1[4], a2[4], a3[4];
            #pragma unroll
            for (int i = 0; i < 4; i++) {
                int m = warp_m * 64 + i * 16;
                a0[i] = As[st][m + ar    ][k0 + ac    ];
                a1[i] = As[st][m + ar + 8][k0 + ac    ];
                a2[i] = As[st][m + ar    ][k0 + ac + 4];
                a3[i] = As[st][m + ar + 8][k0 + ac + 4];
            }
            float b0[4], b1[4];
            #pragma unroll
            for (int j = 0; j < 4; j++) {
                int n = warp_n * 32 + j * 8 + (lane >> 2);
                b0[j] = Bs[st][n][k0 + ac    ];
                b1[j] = Bs[st][n][k0 + ac + 4];
            }
            #pragma unroll
            for (int i = 0; i < 4; i++)
                #pragma unroll
                for (int j = 0; j < 4; j++)
                    mma_tf32(acc[i][j][0], acc[i][j][1], acc[i][j][2], acc[i][j][3],
                             a0[i], a1[i], a2[i], a3[i], b0[j], b1[j]);
        }

        if (c + 1 < NC) {
            __syncthreads();
            const int ns = (c + 1) & 1;
            const int kc = (c + 1) * 16;
            #pragma unroll
            for (int i = 0; i < 2; i++) {
                int r = gr + i * 64;
                As[ns][r][gc + 0] = f2tf32(pa[i].x);
                As[ns][r][gc + 1] = f2tf32(pa[i].y);
                As[ns][r][gc + 2] = f2tf32(pa[i].z);
                As[ns][r][gc + 3] = f2tf32(pa[i].w);
                Bs[ns][r][gc + 0] = f2tf32(pb[i].x * mix_s[kc + gc + 0]);
                Bs[ns][r][gc + 1] = f2tf32(pb[i].y * mix_s[kc + gc + 1]);
                Bs[ns][r][gc + 2] = f2tf32(pb[i].z * mix_s[kc + gc + 2]);
                Bs[ns][r][gc + 3] = f2tf32(pb[i].w * mix_s[kc + gc + 3]);
            }
            __syncthreads();
        }
    }

    // Epilogue: e = exp((acc + cb)/8); write e; accumulate per-row partials.
    const size_t rowbase = (size_t)z * LL;
    const int ar = lane >> 2;
    float rsum[4][2];
    #pragma unroll
    for (int i = 0; i < 4; i++) { rsum[i][0] = 0.0f; rsum[i][1] = 0.0f; }

    #pragma unroll
    for (int i = 0; i < 4; i++) {
        int row = bm + warp_m * 64 + i * 16 + ar;
        #pragma unroll
        for (int j = 0; j < 4; j++) {
            int col = warp_n * 32 + j * 8 + (lane & 3) * 2;
            float cb0 = cb_s[col], cb1 = cb_s[col + 1];
            float2 v0, v1;
            v0.x = __expf((acc[i][j][0] + cb0) * 0.125f);
            v0.y = __expf((acc[i][j][1] + cb1) * 0.125f);
            v1.x = __expf((acc[i][j][2] + cb0) * 0.125f);
            v1.y = __expf((acc[i][j][3] + cb1) * 0.125f);
            rsum[i][0] += v0.x + v0.y;
            rsum[i][1] += v1.x + v1.y;
            *(float2*)(probs + (rowbase + row    ) * SS + bn + col) = v0;
            *(float2*)(probs + (rowbase + row + 8) * SS + bn + col) = v1;
        }
    }
    // reduce over the 4 lanes sharing a row (lane & 3 varies)
    #pragma unroll
    for (int i = 0; i < 4; i++) {
        rsum[i][0] += __shfl_xor_sync(0xffffffffu, rsum[i][0], 1);
        rsum[i][0] += __shfl_xor_sync(0xffffffffu, rsum[i][0], 2);
        rsum[i][1] += __shfl_xor_sync(0xffffffffu, rsum[i][1], 1);
        rsum[i][1] += __shfl_xor_sync(0xffffffffu, rsum[i][1], 2);
    }
    if ((lane & 3) == 0) {
        #pragma unroll
        for (int i = 0; i < 4; i++) {
            int r = warp_m * 64 + i * 16 + ar;
            rs[warp_n][r]     = rsum[i][0];
            rs[warp_n][r + 8] = rsum[i][1];
        }
    }
    __syncthreads();
    if (tid < 128) {
        float s = rs[0][tid] + rs[1][tid] + rs[2][tid] + rs[3][tid];
        psum[(rowbase + bm + tid) * 16 + blockIdx.x] = s;
    }
}

// ---------------------------------------------------------------------------
// ctx via tf32 mma, fused normalization:
//   inv[l] = 1 / sum_n psum[z,l,n]
//   probs[z,l,s] = e * inv   (written back in place — rows are CTA-exclusive)
//   ctx = probs @ Vh
// ---------------------------------------------------------------------------
__global__ __launch_bounds__(256, 2)
void ctx_mma_kernel(float* __restrict__ probs,
                    const float* __restrict__ psum,
                    const float* __restrict__ v,
                    float* __restrict__ ctx) {
    __shared__ float Ps[2][128][SKP];   // [row l][k s]
    __shared__ float Vs[2][16][72];     // [k s][n dv]
    __shared__ float invs[128];

    const int tid  = threadIdx.x;
    const int wid  = tid >> 5;
    const int lane = tid & 31;
    const int warp_m = wid >> 2;
    const int warp_n = wid & 3;

    const int z  = blockIdx.y;     // b*H + h
    const int b  = z >> 3;
    const int h  = z & 7;
    const int bm = blockIdx.x * 128;

    float* P = probs + ((size_t)z * LL + bm) * SS;
    const float* V = v + (size_t)b * SS * DV + h * HD;

    // row inverse sums (deterministic sequential sum of 16 partials)
    if (tid < 128) {
        const float* pp = psum + ((size_t)z * LL + bm + tid) * 16;
        float4 s0 = *(const float4*)(pp + 0);
        float4 s1 = *(const float4*)(pp + 4);
        float4 s2 = *(const float4*)(pp + 8);
        float4 s3 = *(const float4*)(pp + 12);
        float s = ((s0.x + s0.y) + (s0.z + s0.w)) + ((s1.x + s1.y) + (s1.z + s1.w))
                + ((s2.x + s2.y) + (s2.z + s2.w)) + ((s3.x + s3.y) + (s3.z + s3.w));
        invs[tid] = 1.0f / s;
    }
    __syncthreads();

    const int pr = tid >> 2;          // 0..63 (+64)
    const int pc = (tid & 3) * 4;     // 0..12
    const int vs = tid >> 4;          // 0..15
    const int vd = (tid & 15) * 4;    // 0..60

    const float iv0 = invs[pr];
    const float iv1 = invs[pr + 64];

    float acc[4][2][4];
    #pragma unroll
    for (int i = 0; i < 4; i++)
        #pragma unroll
        for (int j = 0; j < 2; j++)
            #pragma unroll
            for (int t = 0; t < 4; t++) acc[i][j][t] = 0.0f;

    float4 pp[2], pv;

    #pragma unroll
    for (int i = 0; i < 2; i++)
        pp[i] = *(const float4*)(P + (size_t)(pr + i * 64) * SS + pc);
    pv = *(const float4*)(V + (size_t)vs * DV + vd);

    #pragma unroll
    for (int i = 0; i < 2; i++) {
        int r = pr + i * 64;
        float iv = (i == 0) ? iv0 : iv1;
        float4 nv = make_float4(pp[i].x * iv, pp[i].y * iv, pp[i].z * iv, pp[i].w * iv);
        *(float4*)(P + (size_t)r * SS + pc) = nv;   // normalized probs out
        float4 t = make_float4(f2tf32(nv.x), f2tf32(nv.y), f2tf32(nv.z), f2tf32(nv.w));
        *(float4*)&Ps[0][r][pc] = t;
    }
    {
        float4 t = make_float4(f2tf32(pv.x), f2tf32(pv.y), f2tf32(pv.z), f2tf32(pv.w));
        *(float4*)&Vs[0][vs][vd] = t;
    }
    __syncthreads();

    const int NC = SS / 16;   // 128 chunks
    for (int c = 0; c < NC; c++) {
        if (c + 1 < NC) {
            int kc = (c + 1) * 16;
            #pragma unroll
            for (int i = 0; i < 2; i++)
                pp[i] = *(const float4*)(P + (size_t)(pr + i * 64) * SS + kc + pc);
            pv = *(const float4*)(V + (size_t)(kc + vs) * DV + vd);
        }

        const int st = c & 1;
        #pragma unroll
        for (int kk = 0; kk < 2; kk++) {
            const int k0 = kk * 8;
            const int ar = lane >> 2;
            const int ac = lane & 3;
            float a0[4], a1[4], a2[4], a3[4];
            #pragma unroll
            for (int i = 0; i < 4; i++) {
                int m = warp_m * 64 + i * 16;
                a0[i] = Ps[st][m + ar    ][k0 + ac    ];
                a1[i] = Ps[st][m + ar + 8][k0 + ac    ];
                a2[i] = Ps[st][m + ar    ][k0 + ac + 4];
                a3[i] = Ps[st][m + ar + 8][k0 + ac + 4];
            }
            float b0[2], b1[2];
            #pragma unroll
            for (int j = 0; j < 2; j++) {
                int n = warp_n * 16 + j * 8 + (lane >> 2);
                b0[j] = Vs[st][k0 + ac    ][n];
                b1[j] = Vs[st][k0 + ac + 4][n];
            }
            #pragma unroll
            for (int i = 0; i < 4; i++)
                #pragma unroll
                for (int j = 0; j < 2; j++)
                    mma_tf32(acc[i][j][0], acc[i][j][1], acc[i][j][2], acc[i][j][3],
                             a0[i], a1[i], a2[i], a3[i], b0[j], b1[j]);
        }

        if (c + 1 < NC) {
            __syncthreads();
            const int ns = (c + 1) & 1;
            const int kc = (c + 1) * 16;
            #pragma unroll
            for (int i = 0; i < 2; i++) {
                int r = pr + i * 64;
                float iv = (i == 0) ? iv0 : iv1;
                float4 nv = make_float4(pp[i].x * iv, pp[i].y * iv, pp[i].z * iv, pp[i].w * iv);
                *(float4*)(P + (size_t)r * SS + kc + pc) = nv;
                float4 t = make_float4(f2tf32(nv.x), f2tf32(nv.y), f2tf32(nv.z), f2tf32(nv.w));
                *(float4*)&Ps[ns][r][pc] = t;
            }
            {
                float4 t = make_float4(f2tf32(pv.x), f2tf32(pv.y), f2tf32(pv.z), f2tf32(pv.w));
                *(float4*)&Vs[ns][vs][vd] = t;
            }
            __syncthreads();
        }
    }

    #pragma unroll
    for (int i = 0; i < 4; i++) {
        int row = bm + warp_m * 64 + i * 16 + (lane >> 2);
        #pragma unroll
        for (int j = 0; j < 2; j++) {
            int col = warp_n * 16 + j * 8 + (lane & 3) * 2;
            float2 v0, v1;
            v0.x = acc[i][j][0]; v0.y = acc[i][j][1];
            v1.x = acc[i][j][2]; v1.y = acc[i][j][3];
            *(float2*)(ctx + (size_t)(b * LL + row) * DV + h * HD + col) = v0;
            *(float2*)(ctx + (size_t)(b * LL + row + 8) * DV + h * HD + col) = v1;
        }
    }
}

// ---------------------------------------------------------------------------
// cb kernel (unchanged)
// ---------------------------------------------------------------------------
__global__ void cb_kernel(const float* __restrict__ keys,
                          const float* __restrict__ Wcb,
                          float* __restrict__ cb) {
    const int bs = blockIdx.x;
    const int b  = bs / SS;
    const int s  = bs % SS;
    __shared__ float krow[DIN];
    const int tid = threadIdx.x;
    for (int i = tid; i < DIN; i += 256) krow[i] = keys[(size_t)bs * DIN + i];
    __syncthreads();
    const int w    = tid >> 5;
    const int lane = tid & 31;
    float sum = 0.0f;
    #pragma unroll 4
    for (int i = lane; i < DIN; i += 32) sum += krow[i] * Wcb[w * DIN + i];
    #pragma unroll
    for (int o = 16; o > 0; o >>= 1) sum += __shfl_down_sync(0xffffffffu, sum, o);
    if (lane == 0) cb[(size_t)(b * HH + w) * SS + s] = sum;
}

// ---------------------------------------------------------------------------
extern "C" void kernel_launch(void* const* d_in, const int* in_sizes, int n_in,
                              void* d_out, int out_size) {
    const float* queries = (const float*)d_in[0];
    const float* keys    = (const float*)d_in[1];
    const float* values  = (const float*)d_in[2];
    const float* Wq      = (const float*)d_in[4];
    const float* Wk      = (const float*)d_in[5];
    const float* Wv      = (const float*)d_in[6];
    const float* bv      = (const float*)d_in[7];
    const float* Wcb     = (const float*)d_in[8];
    const float* mixing  = (const float*)d_in[9];
    const float* Wd      = (const float*)d_in[10];
    const float* bd      = (const float*)d_in[11];

    float* out = (float*)d_out;

    void *pq, *pk, *pv, *pcb, *pctx, *ppsum, *pprobs;
    cudaGetSymbolAddress(&pq,    g_q);
    cudaGetSymbolAddress(&pk,    g_k);
    cudaGetSymbolAddress(&pv,    g_v);
    cudaGetSymbolAddress(&pcb,   g_cb);
    cudaGetSymbolAddress(&pctx,  g_ctx);
    cudaGetSymbolAddress(&ppsum, g_psum);
    cudaGetSymbolAddress(&pprobs, g_probs);

    float* probs;
    if ((long)out_size >= OUT_ELEMS + PROB_ELEMS) probs = out + OUT_ELEMS;
    else                                           probs = (float*)pprobs;

    const int M = BB * LL;

    cb_kernel<<<BB * SS, 256>>>(keys, Wcb, (float*)pcb);

    dim3 gproj(DOUT / 128, M / 128);
    gemm_mma_kernel<false><<<gproj, 256>>>(queries, Wq, nullptr, (float*)pq, M, DK,  DIN);
    gemm_mma_kernel<false><<<gproj, 256>>>(keys,    Wk, nullptr, (float*)pk, M, DK,  DIN);
    gemm_mma_kernel<true ><<<gproj, 256>>>(values,  Wv, bv,      (float*)pv, M, DV,  DIN);

    // scores (exp + partial rowsums fused)
    dim3 gsc(SS / 128, LL / 128, BB * HH);
    scores_mma_kernel<<<gsc, 256>>>((const float*)pq, (const float*)pk,
                                    mixing, (const float*)pcb, probs, (float*)ppsum);

    // ctx with fused normalization (writes normalized probs in place)
    dim3 gctx(LL / 128, BB * HH);
    ctx_mma_kernel<<<gctx, 256>>>(probs, (const float*)ppsum, (const float*)pv, (float*)pctx);

    gemm_mma_kernel<true><<<gproj, 256>>>((const float*)pctx, Wd, bd, out, M, DOUT, DV);
}

// round 7
// speedup vs baseline: 1.2364x; 1.2364x over previous
#include <cuda_runtime.h>
#include <cuda_bf16.h>
#include <cstdint>

// Problem constants
#define BB   2
#define LL   2048
#define SS   2048
#define DIN  512
#define DK   512
#define DV   512
#define DOUT 512
#define HH   8
#define HD   64

#define OUT_ELEMS  ((long)BB * LL * DOUT)
#define PROB_ELEMS ((long)BB * HH * (long)LL * (long)SS)

// Scratch (device globals — no runtime allocation allowed)
__device__ float g_qm [BB * HH * (long)LL * DK];    // pre-mixed q per head (64 MB)
__device__ float g_k  [BB * SS * DK];
__device__ float g_v  [BB * SS * DV];
__device__ float g_cb [BB * HH * SS];
__device__ float g_ctx[BB * LL * DV];
__device__ float g_psum[BB * HH * (long)LL * 16];
__device__ float g_probs[BB * HH * (long)LL * SS];

// ---------------------------------------------------------------------------
// tf32 helpers (plain sm_103 target — mma.sync is the tensor path)
// ---------------------------------------------------------------------------
__device__ __forceinline__ float f2tf32(float v) {
    uint32_t r;
    asm("cvt.rna.tf32.f32 %0, %1;" : "=r"(r) : "f"(v));
    return __uint_as_float(r);
}

__device__ __forceinline__ void mma_tf32(float& c0, float& c1, float& c2, float& c3,
                                         float a0, float a1, float a2, float a3,
                                         float b0, float b1) {
    asm volatile(
        "mma.sync.aligned.m16n8k8.row.col.f32.tf32.tf32.f32 "
        "{%0,%1,%2,%3}, {%4,%5,%6,%7}, {%8,%9}, {%0,%1,%2,%3};"
        : "+f"(c0), "+f"(c1), "+f"(c2), "+f"(c3)
        : "r"(__float_as_uint(a0)), "r"(__float_as_uint(a1)),
          "r"(__float_as_uint(a2)), "r"(__float_as_uint(a3)),
          "r"(__float_as_uint(b0)), "r"(__float_as_uint(b1)));
}

#define CP_ASYNC16(dst_u32, src) \
    asm volatile("cp.async.cg.shared.global [%0], [%1], 16;" :: "r"(dst_u32), "l"(src))
#define CP_COMMIT() asm volatile("cp.async.commit_group;" ::: "memory")
#define CP_WAIT2()  asm volatile("cp.async.wait_group 2;" ::: "memory")

#define SKP 20   // padded smem stride for the register-staged kernels

// ---------------------------------------------------------------------------
// Generic tf32 mma GEMM: C[M,N] = A[M,K] * W[N,K]^T (+ bias[n])  (unchanged)
// ---------------------------------------------------------------------------
template <bool HAS_BIAS>
__global__ __launch_bounds__(256, 2)
void gemm_mma_kernel(const float* __restrict__ A,
                     const float* __restrict__ W,
                     const float* __restrict__ bias,
                     float* __restrict__ C,
                     int M, int N, int K) {
    __shared__ float As[2][128][SKP];
    __shared__ float Bs[2][128][SKP];
    __shared__ float bias_s[128];

    const int tid  = threadIdx.x;
    const int wid  = tid >> 5;
    const int lane = tid & 31;
    const int warp_m = wid >> 2;
    const int warp_n = wid & 3;

    const int bm = blockIdx.y * 128;
    const int bn = blockIdx.x * 128;

    const float* Ag = A + (size_t)bm * K;
    const float* Wg = W + (size_t)bn * K;

    if (HAS_BIAS && tid < 128) bias_s[tid] = bias[bn + tid];
    __syncthreads();

    const int gr = tid >> 2;
    const int gc = (tid & 3) * 4;

    float acc[4][4][4];
    #pragma unroll
    for (int i = 0; i < 4; i++)
        #pragma unroll
        for (int j = 0; j < 4; j++)
            #pragma unroll
            for (int t = 0; t < 4; t++) acc[i][j][t] = 0.0f;

    float4 pa[2], pb[2];

    #pragma unroll
    for (int i = 0; i < 2; i++) {
        pa[i] = *(const float4*)(Ag + (size_t)(gr + i * 64) * K + gc);
        pb[i] = *(const float4*)(Wg + (size_t)(gr + i * 64) * K + gc);
    }
    #pragma unroll
    for (int i = 0; i < 2; i++) {
        int r = gr + i * 64;
        float4 ta = make_float4(f2tf32(pa[i].x), f2tf32(pa[i].y), f2tf32(pa[i].z), f2tf32(pa[i].w));
        float4 tb = make_float4(f2tf32(pb[i].x), f2tf32(pb[i].y), f2tf32(pb[i].z), f2tf32(pb[i].w));
        *(float4*)&As[0][r][gc] = ta;
        *(float4*)&Bs[0][r][gc] = tb;
    }
    __syncthreads();

    const int NC = K / 16;
    for (int c = 0; c < NC; c++) {
        if (c + 1 < NC) {
            int kc = (c + 1) * 16;
            #pragma unroll
            for (int i = 0; i < 2; i++) {
                pa[i] = *(const float4*)(Ag + (size_t)(gr + i * 64) * K + kc + gc);
                pb[i] = *(const float4*)(Wg + (size_t)(gr + i * 64) * K + kc + gc);
            }
        }

        const int st = c & 1;
        #pragma unroll
        for (int kk = 0; kk < 2; kk++) {
            const int k0 = kk * 8;
            const int ar = lane >> 2;
            const int ac = lane & 3;
            float a0[4], a1[4], a2[4], a3[4];
            #pragma unroll
            for (int i = 0; i < 4; i++) {
                int m = warp_m * 64 + i * 16;
                a0[i] = As[st][m + ar    ][k0 + ac    ];
                a1[i] = As[st][m + ar + 8][k0 + ac    ];
                a2[i] = As[st][m + ar    ][k0 + ac + 4];
                a3[i] = As[st][m + ar + 8][k0 + ac + 4];
            }
            float b0[4], b1[4];
            #pragma unroll
            for (int j = 0; j < 4; j++) {
                int n = warp_n * 32 + j * 8 + (lane >> 2);
                b0[j] = Bs[st][n][k0 + ac    ];
                b1[j] = Bs[st][n][k0 + ac + 4];
            }
            #pragma unroll
            for (int i = 0; i < 4; i++)
                #pragma unroll
                for (int j = 0; j < 4; j++)
                    mma_tf32(acc[i][j][0], acc[i][j][1], acc[i][j][2], acc[i][j][3],
                             a0[i], a1[i], a2[i], a3[i], b0[j], b1[j]);
        }

        if (c + 1 < NC) {
            __syncthreads();
            const int ns = (c + 1) & 1;
            #pragma unroll
            for (int i = 0; i < 2; i++) {
                int r = gr + i * 64;
                float4 ta = make_float4(f2tf32(pa[i].x), f2tf32(pa[i].y), f2tf32(pa[i].z), f2tf32(pa[i].w));
                float4 tb = make_float4(f2tf32(pb[i].x), f2tf32(pb[i].y), f2tf32(pb[i].z), f2tf32(pb[i].w));
                *(float4*)&As[ns][r][gc] = ta;
                *(float4*)&Bs[ns][r][gc] = tb;
            }
            __syncthreads();
        }
    }

    #pragma unroll
    for (int i = 0; i < 4; i++) {
        int row = bm + warp_m * 64 + i * 16 + (lane >> 2);
        #pragma unroll
        for (int j = 0; j < 4; j++) {
            int col = warp_n * 32 + j * 8 + (lane & 3) * 2;
            float bb0 = HAS_BIAS ? bias_s[col]     : 0.0f;
            float bb1 = HAS_BIAS ? bias_s[col + 1] : 0.0f;
            float2 v0, v1;
            v0.x = acc[i][j][0] + bb0; v0.y = acc[i][j][1] + bb1;
            v1.x = acc[i][j][2] + bb0; v1.y = acc[i][j][3] + bb1;
            *(float2*)(C + (size_t)row * N + bn + col) = v0;
            *(float2*)(C + (size_t)(row + 8) * N + bn + col) = v1;
        }
    }
}

// ---------------------------------------------------------------------------
// q-projection with pre-mixed per-head outputs:
//   qm[(b,h), l, e] = (queries @ Wq^T)[b,l,e] * mixing[h,e]
// Same mainloop as gemm_mma_kernel<false>; epilogue fans out 8 scaled copies.
// grid = (DK/128, (B*L)/128)
// ---------------------------------------------------------------------------
__global__ __launch_bounds__(256, 2)
void qproj_mma_kernel(const float* __restrict__ A,
                      const float* __restrict__ W,
                      const float* __restrict__ mixing,
                      float* __restrict__ qm) {
    __shared__ float As[2][128][SKP];
    __shared__ float Bs[2][128][SKP];
    __shared__ float mix_s[8][128];

    const int tid  = threadIdx.x;
    const int wid  = tid >> 5;
    const int lane = tid & 31;
    const int warp_m = wid >> 2;
    const int warp_n = wid & 3;

    const int bm = blockIdx.y * 128;
    const int bn = blockIdx.x * 128;
    const int K = DIN;

    const float* Ag = A + (size_t)bm * K;
    const float* Wg = W + (size_t)bn * K;

    for (int i = tid; i < 8 * 128; i += 256)
        mix_s[i >> 7][i & 127] = mixing[(i >> 7) * DK + bn + (i & 127)];
    __syncthreads();

    const int gr = tid >> 2;
    const int gc = (tid & 3) * 4;

    float acc[4][4][4];
    #pragma unroll
    for (int i = 0; i < 4; i++)
        #pragma unroll
        for (int j = 0; j < 4; j++)
            #pragma unroll
            for (int t = 0; t < 4; t++) acc[i][j][t] = 0.0f;

    float4 pa[2], pb[2];

    #pragma unroll
    for (int i = 0; i < 2; i++) {
        pa[i] = *(const float4*)(Ag + (size_t)(gr + i * 64) * K + gc);
        pb[i] = *(const float4*)(Wg + (size_t)(gr + i * 64) * K + gc);
    }
    #pragma unroll
    for (int i = 0; i < 2; i++) {
        int r = gr + i * 64;
        float4 ta = make_float4(f2tf32(pa[i].x), f2tf32(pa[i].y), f2tf32(pa[i].z), f2tf32(pa[i].w));
        float4 tb = make_float4(f2tf32(pb[i].x), f2tf32(pb[i].y), f2tf32(pb[i].z), f2tf32(pb[i].w));
        *(float4*)&As[0][r][gc] = ta;
        *(float4*)&Bs[0][r][gc] = tb;
    }
    __syncthreads();

    const int NC = K / 16;
    for (int c = 0; c < NC; c++) {
        if (c + 1 < NC) {
            int kc = (c + 1) * 16;
            #pragma unroll
            for (int i = 0; i < 2; i++) {
                pa[i] = *(const float4*)(Ag + (size_t)(gr + i * 64) * K + kc + gc);
                pb[i] = *(const float4*)(Wg + (size_t)(gr + i * 64) * K + kc + gc);
            }
        }

        const int st = c & 1;
        #pragma unroll
        for (int kk = 0; kk < 2; kk++) {
            const int k0 = kk * 8;
            const int ar = lane >> 2;
            const int ac = lane & 3;
            float a0[4], a1[4], a2[4], a3[4];
            #pragma unroll
            for (int i = 0; i < 4; i++) {
                int m = warp_m * 64 + i * 16;
                a0[i] = As[st][m + ar    ][k0 + ac    ];
                a1[i] = As[st][m + ar + 8][k0 + ac    ];
                a2[i] = As[st][m + ar    ][k0 + ac + 4];
                a3[i] = As[st][m + ar + 8][k0 + ac + 4];
            }
            float b0[4], b1[4];
            #pragma unroll
            for (int j = 0; j < 4; j++) {
                int n = warp_n * 32 + j * 8 + (lane >> 2);
                b0[j] = Bs[st][n][k0 + ac    ];
                b1[j] = Bs[st][n][k0 + ac + 4];
            }
            #pragma unroll
            for (int i = 0; i < 4; i++)
                #pragma unroll
                for (int j = 0; j < 4; j++)
                    mma_tf32(acc[i][j][0], acc[i][j][1], acc[i][j][2], acc[i][j][3],
                             a0[i], a1[i], a2[i], a3[i], b0[j], b1[j]);
        }

        if (c + 1 < NC) {
            __syncthreads();
            const int ns = (c + 1) & 1;
            #pragma unroll
            for (int i = 0; i < 2; i++) {
                int r = gr + i * 64;
                float4 ta = make_float4(f2tf32(pa[i].x), f2tf32(pa[i].y), f2tf32(pa[i].z), f2tf32(pa[i].w));
                float4 tb = make_float4(f2tf32(pb[i].x), f2tf32(pb[i].y), f2tf32(pb[i].z), f2tf32(pb[i].w));
                *(float4*)&As[ns][r][gc] = ta;
                *(float4*)&Bs[ns][r][gc] = tb;
            }
            __syncthreads();
        }
    }

    // Epilogue: fan out 8 mixed copies. Whole CTA is within one batch b.
    const int bq = bm >> 11;               // batch index
    #pragma unroll
    for (int i = 0; i < 4; i++) {
        int row = bm + warp_m * 64 + i * 16 + (lane >> 2);
        int l = row & (LL - 1);
        #pragma unroll
        for (int j = 0; j < 4; j++) {
            int col = warp_n * 32 + j * 8 + (lane & 3) * 2;
            #pragma unroll
            for (int h = 0; h < 8; h++) {
                float m0 = mix_s[h][col], m1 = mix_s[h][col + 1];
                float2 v0, v1;
                v0.x = acc[i][j][0] * m0; v0.y = acc[i][j][1] * m1;
                v1.x = acc[i][j][2] * m0; v1.y = acc[i][j][3] * m1;
                float* base = qm + ((size_t)(bq * HH + h) * LL) * DK + bn + col;
                *(float2*)(base + (size_t)l * DK)       = v0;
                *(float2*)(base + (size_t)(l + 8) * DK) = v1;
            }
        }
    }
}

// ---------------------------------------------------------------------------
// Scores: pure tf32 GEMM with cp.async 3-stage pipeline, BK=32.
//   e[z,l,s] = exp((qm_z[l,:] . k_b[s,:] + cb[z,s]) / 8)   -> probs
//   psum[z,l,cta_n] = partial row sums (deterministic)
// XOR-swizzled 128x32 tiles, no padding, no cvt (HW tf32 truncation).
// grid = (S/128, L/128, B*H), 256 threads, 96KB dynamic smem.
// ---------------------------------------------------------------------------
__global__ __launch_bounds__(256, 2)
void scores_mma_kernel(const float* __restrict__ qm,
                       const float* __restrict__ kmat,
                       const float* __restrict__ cb,
                       float* __restrict__ probs,
                       float* __restrict__ psum) {
    extern __shared__ float sm[];   // [3 stages][A:128x32 | B:128x32]
    __shared__ float cb_s[128];
    __shared__ float rs[4][130];

    const int tid  = threadIdx.x;
    const int wid  = tid >> 5;
    const int lane = tid & 31;
    const int warp_m = wid >> 2;
    const int warp_n = wid & 3;

    const int z  = blockIdx.z;
    const int b  = z >> 3;
    const int bm = blockIdx.y * 128;
    const int bn = blockIdx.x * 128;

    const float* Aq = qm   + (size_t)z * LL * DK + (size_t)bm * DK;
    const float* Bk = kmat + (size_t)b * SS * DK + (size_t)bn * DK;

    if (tid < 128) cb_s[tid] = cb[(size_t)z * SS + bn + tid];

    const uint32_t sbase = (uint32_t)__cvta_generic_to_shared(sm);

    // cp.async issue of chunk cidx (32 k-cols) into stage cidx%3
    auto issue = [&](int cidx) {
        const uint32_t st_off = (uint32_t)(cidx % 3) * 8192u * 4u;
        const int kc = cidx * 32;
        #pragma unroll
        for (int i = 0; i < 4; i++) {
            int idx = tid + i * 256;          // 0..1023
            int r   = idx >> 3;               // row 0..127
            int gcf = (idx & 7) * 4;          // col 0,4,...,28
            int sc  = gcf ^ ((r & 7) << 2);   // XOR swizzle
            uint32_t da = sbase + st_off + (uint32_t)(r * 32 + sc) * 4u;
            CP_ASYNC16(da,          Aq + (size_t)r * DK + kc + gcf);
            CP_ASYNC16(da + 16384u, Bk + (size_t)r * DK + kc + gcf);
        }
    };

    float acc[4][4][4];
    #pragma unroll
    for (int i = 0; i < 4; i++)
        #pragma unroll
        for (int j = 0; j < 4; j++)
            #pragma unroll
            for (int t = 0; t < 4; t++) acc[i][j][t] = 0.0f;

    const int NC = DK / 32;   // 16 chunks
    issue(0); CP_COMMIT();
    issue(1); CP_COMMIT();

    const int ar = lane >> 2;
    const int ac = lane & 3;

    for (int c = 0; c < NC; c++) {
        if (c + 2 < NC) issue(c + 2);
        CP_COMMIT();              // real or empty group — keeps wait arithmetic fixed
        CP_WAIT2();
        __syncthreads();

        const float* As = sm + (c % 3) * 8192;
        const float* Bs = As + 4096;

        #pragma unroll
        for (int kk = 0; kk < 4; kk++) {
            const int k0 = kk * 8;
            const int sc0 = (k0 + ac)     ^ (ar << 2);
            const int sc1 = (k0 + ac + 4) ^ (ar << 2);
            float a0[4], a1[4], a2[4], a3[4];
            #pragma unroll
            for (int i = 0; i < 4; i++) {
                int m = warp_m * 64 + i * 16;
                a0[i] = As[(m + ar    ) * 32 + sc0];
                a1[i] = As[(m + ar + 8) * 32 + sc0];
                a2[i] = As[(m + ar    ) * 32 + sc1];
                a3[i] = As[(m + ar + 8) * 32 + sc1];
            }
            float b0[4], b1[4];
            #pragma unroll
            for (int j = 0; j < 4; j++) {
                int n = warp_n * 32 + j * 8 + ar;
                b0[j] = Bs[n * 32 + sc0];
                b1[j] = Bs[n * 32 + sc1];
            }
            #pragma unroll
            for (int i = 0; i < 4; i++)
                #pragma unroll
                for (int j = 0; j < 4; j++)
                    mma_tf32(acc[i][j][0], acc[i][j][1], acc[i][j][2], acc[i][j][3],
                             a0[i], a1[i], a2[i], a3[i], b0[j], b1[j]);
        }
        __syncthreads();
    }

    // Epilogue: e = exp((acc + cb)/8); write e; per-row partial sums.
    const size_t rowbase = (size_t)z * LL;
    float rsum[4][2];
    #pragma unroll
    for (int i = 0; i < 4; i++) { rsum[i][0] = 0.0f; rsum[i][1] = 0.0f; }

    #pragma unroll
    for (int i = 0; i < 4; i++) {
        int row = bm + warp_m * 64 + i * 16 + ar;
        #pragma unroll
        for (int j = 0; j < 4; j++) {
            int col = warp_n * 32 + j * 8 + (lane & 3) * 2;
            float cb0 = cb_s[col], cb1 = cb_s[col + 1];
            float2 v0, v1;
            v0.x = __expf((acc[i][j][0] + cb0) * 0.125f);
            v0.y = __expf((acc[i][j][1] + cb1) * 0.125f);
            v1.x = __expf((acc[i][j][2] + cb0) * 0.125f);
            v1.y = __expf((acc[i][j][3] + cb1) * 0.125f);
            rsum[i][0] += v0.x + v0.y;
            rsum[i][1] += v1.x + v1.y;
            *(float2*)(probs + (rowbase + row    ) * SS + bn + col) = v0;
            *(float2*)(probs + (rowbase + row + 8) * SS + bn + col) = v1;
        }
    }
    #pragma unroll
    for (int i = 0; i < 4; i++) {
        rsum[i][0] += __shfl_xor_sync(0xffffffffu, rsum[i][0], 1);
        rsum[i][0] += __shfl_xor_sync(0xffffffffu, rsum[i][0], 2);
        rsum[i][1] += __shfl_xor_sync(0xffffffffu, rsum[i][1], 1);
        rsum[i][1] += __shfl_xor_sync(0xffffffffu, rsum[i][1], 2);
    }
    if ((lane & 3) == 0) {
        #pragma unroll
        for (int i = 0; i < 4; i++) {
            int r = warp_m * 64 + i * 16 + ar;
            rs[warp_n][r]     = rsum[i][0];
            rs[warp_n][r + 8] = rsum[i][1];
        }
    }
    __syncthreads();
    if (tid < 128) {
        float s = rs[0][tid] + rs[1][tid] + rs[2][tid] + rs[3][tid];
        psum[(rowbase + bm + tid) * 16 + blockIdx.x] = s;
    }
}

// ---------------------------------------------------------------------------
// ctx via tf32 mma with fused normalization (unchanged from R6)
// ---------------------------------------------------------------------------
__global__ __launch_bounds__(256, 2)
void ctx_mma_kernel(float* __restrict__ probs,
                    const float* __restrict__ psum,
                    const float* __restrict__ v,
                    float* __restrict__ ctx) {
    __shared__ float Ps[2][128][SKP];
    __shared__ float Vs[2][16][72];
    __shared__ float invs[128];

    const int tid  = threadIdx.x;
    const int wid  = tid >> 5;
    const int lane = tid & 31;
    const int warp_m = wid >> 2;
    const int warp_n = wid & 3;

    const int z  = blockIdx.y;
    const int b  = z >> 3;
    const int h  = z & 7;
    const int bm = blockIdx.x * 128;

    float* P = probs + ((size_t)z * LL + bm) * SS;
    const float* V = v + (size_t)b * SS * DV + h * HD;

    if (tid < 128) {
        const float* pp = psum + ((size_t)z * LL + bm + tid) * 16;
        float4 s0 = *(const float4*)(pp + 0);
        float4 s1 = *(const float4*)(pp + 4);
        float4 s2 = *(const float4*)(pp + 8);
        float4 s3 = *(const float4*)(pp + 12);
        float s = ((s0.x + s0.y) + (s0.z + s0.w)) + ((s1.x + s1.y) + (s1.z + s1.w))
                + ((s2.x + s2.y) + (s2.z + s2.w)) + ((s3.x + s3.y) + (s3.z + s3.w));
        invs[tid] = 1.0f / s;
    }
    __syncthreads();

    const int pr = tid >> 2;
    const int pc = (tid & 3) * 4;
    const int vs = tid >> 4;
    const int vd = (tid & 15) * 4;

    const float iv0 = invs[pr];
    const float iv1 = invs[pr + 64];

    float acc[4][2][4];
    #pragma unroll
    for (int i = 0; i < 4; i++)
        #pragma unroll
        for (int j = 0; j < 2; j++)
            #pragma unroll
            for (int t = 0; t < 4; t++) acc[i][j][t] = 0.0f;

    float4 pp[2], pv;

    #pragma unroll
    for (int i = 0; i < 2; i++)
        pp[i] = *(const float4*)(P + (size_t)(pr + i * 64) * SS + pc);
    pv = *(const float4*)(V + (size_t)vs * DV + vd);

    #pragma unroll
    for (int i = 0; i < 2; i++) {
        int r = pr + i * 64;
        float iv = (i == 0) ? iv0 : iv1;
        float4 nv = make_float4(pp[i].x * iv, pp[i].y * iv, pp[i].z * iv, pp[i].w * iv);
        *(float4*)(P + (size_t)r * SS + pc) = nv;
        float4 t = make_float4(f2tf32(nv.x), f2tf32(nv.y), f2tf32(nv.z), f2tf32(nv.w));
        *(float4*)&Ps[0][r][pc] = t;
    }
    {
        float4 t = make_float4(f2tf32(pv.x), f2tf32(pv.y), f2tf32(pv.z), f2tf32(pv.w));
        *(float4*)&Vs[0][vs][vd] = t;
    }
    __syncthreads();

    const int NC = SS / 16;
    for (int c = 0; c < NC; c++) {
        if (c + 1 < NC) {
            int kc = (c + 1) * 16;
            #pragma unroll
            for (int i = 0; i < 2; i++)
                pp[i] = *(const float4*)(P + (size_t)(pr + i * 64) * SS + kc + pc);
            pv = *(const float4*)(V + (size_t)(kc + vs) * DV + vd);
        }

        const int st = c & 1;
        #pragma unroll
        for (int kk = 0; kk < 2; kk++) {
            const int k0 = kk * 8;
            const int ar = lane >> 2;
            const int ac = lane & 3;
            float a0[4], a1[4], a2[4], a3[4];
            #pragma unroll
            for (int i = 0; i < 4; i++) {
                int m = warp_m * 64 + i * 16;
                a0[i] = Ps[st][m + ar    ][k0 + ac    ];
                a1[i] = Ps[st][m + ar + 8][k0 + ac    ];
                a2[i] = Ps[st][m + ar    ][k0 + ac + 4];
                a3[i] = Ps[st][m + ar + 8][k0 + ac + 4];
            }
            float b0[2], b1[2];
            #pragma unroll
            for (int j = 0; j < 2; j++) {
                int n = warp_n * 16 + j * 8 + (lane >> 2);
                b0[j] = Vs[st][k0 + ac    ][n];
                b1[j] = Vs[st][k0 + ac + 4][n];
            }
            #pragma unroll
            for (int i = 0; i < 4; i++)
                #pragma unroll
                for (int j = 0; j < 2; j++)
                    mma_tf32(acc[i][j][0], acc[i][j][1], acc[i][j][2], acc[i][j][3],
                             a0[i], a1[i], a2[i], a3[i], b0[j], b1[j]);
        }

        if (c + 1 < NC) {
            __syncthreads();
            const int ns = (c + 1) & 1;
            const int kc = (c + 1) * 16;
            #pragma unroll
            for (int i = 0; i < 2; i++) {
                int r = pr + i * 64;
                float iv = (i == 0) ? iv0 : iv1;
                float4 nv = make_float4(pp[i].x * iv, pp[i].y * iv, pp[i].z * iv, pp[i].w * iv);
                *(float4*)(P + (size_t)r * SS + kc + pc) = nv;
                float4 t = make_float4(f2tf32(nv.x), f2tf32(nv.y), f2tf32(nv.z), f2tf32(nv.w));
                *(float4*)&Ps[ns][r][pc] = t;
            }
            {
                float4 t = make_float4(f2tf32(pv.x), f2tf32(pv.y), f2tf32(pv.z), f2tf32(pv.w));
                *(float4*)&Vs[ns][vs][vd] = t;
            }
            __syncthreads();
        }
    }

    #pragma unroll
    for (int i = 0; i < 4; i++) {
        int row = bm + warp_m * 64 + i * 16 + (lane >> 2);
        #pragma unroll
        for (int j = 0; j < 2; j++) {
            int col = warp_n * 16 + j * 8 + (lane & 3) * 2;
            float2 v0, v1;
            v0.x = acc[i][j][0]; v0.y = acc[i][j][1];
            v1.x = acc[i][j][2]; v1.y = acc[i][j][3];
            *(float2*)(ctx + (size_t)(b * LL + row) * DV + h * HD + col) = v0;
            *(float2*)(ctx + (size_t)(b * LL + row + 8) * DV + h * HD + col) = v1;
        }
    }
}

// ---------------------------------------------------------------------------
// cb kernel (unchanged)
// ---------------------------------------------------------------------------
__global__ void cb_kernel(const float* __restrict__ keys,
                          const float* __restrict__ Wcb,
                          float* __restrict__ cb) {
    const int bs = blockIdx.x;
    const int b  = bs / SS;
    const int s  = bs % SS;
    __shared__ float krow[DIN];
    const int tid = threadIdx.x;
    for (int i = tid; i < DIN; i += 256) krow[i] = keys[(size_t)bs * DIN + i];
    __syncthreads();
    const int w    = tid >> 5;
    const int lane = tid & 31;
    float sum = 0.0f;
    #pragma unroll 4
    for (int i = lane; i < DIN; i += 32) sum += krow[i] * Wcb[w * DIN + i];
    #pragma unroll
    for (int o = 16; o > 0; o >>= 1) sum += __shfl_down_sync(0xffffffffu, sum, o);
    if (lane == 0) cb[(size_t)(b * HH + w) * SS + s] = sum;
}

// ---------------------------------------------------------------------------
extern "C" void kernel_launch(void* const* d_in, const int* in_sizes, int n_in,
                              void* d_out, int out_size) {
    const float* queries = (const float*)d_in[0];
    const float* keys    = (const float*)d_in[1];
    const float* values  = (const float*)d_in[2];
    const float* Wq      = (const float*)d_in[4];
    const float* Wk      = (const float*)d_in[5];
    const float* Wv      = (const float*)d_in[6];
    const float* bv      = (const float*)d_in[7];
    const float* Wcb     = (const float*)d_in[8];
    const float* mixing  = (const float*)d_in[9];
    const float* Wd      = (const float*)d_in[10];
    const float* bd      = (const float*)d_in[11];

    float* out = (float*)d_out;

    void *pqm, *pk, *pv, *pcb, *pctx, *ppsum, *pprobs;
    cudaGetSymbolAddress(&pqm,   g_qm);
    cudaGetSymbolAddress(&pk,    g_k);
    cudaGetSymbolAddress(&pv,    g_v);
    cudaGetSymbolAddress(&pcb,   g_cb);
    cudaGetSymbolAddress(&pctx,  g_ctx);
    cudaGetSymbolAddress(&ppsum, g_psum);
    cudaGetSymbolAddress(&pprobs, g_probs);

    float* probs;
    if ((long)out_size >= OUT_ELEMS + PROB_ELEMS) probs = out + OUT_ELEMS;
    else                                           probs = (float*)pprobs;

    const int SC_SMEM = 3 * 8192 * 4;   // 96 KB dynamic
    cudaFuncSetAttribute(scores_mma_kernel,
                         cudaFuncAttributeMaxDynamicSharedMemorySize, SC_SMEM);

    const int M = BB * LL;

    cb_kernel<<<BB * SS, 256>>>(keys, Wcb, (float*)pcb);

    dim3 gproj(DOUT / 128, M / 128);
    qproj_mma_kernel<<<gproj, 256>>>(queries, Wq, mixing, (float*)pqm);
    gemm_mma_kernel<false><<<gproj, 256>>>(keys,   Wk, nullptr, (float*)pk, M, DK, DIN);
    gemm_mma_kernel<true ><<<gproj, 256>>>(values, Wv, bv,      (float*)pv, M, DV, DIN);

    dim3 gsc(SS / 128, LL / 128, BB * HH);
    scores_mma_kernel<<<gsc, 256, SC_SMEM>>>((const float*)pqm, (const float*)pk,
                                             (const float*)pcb, probs, (float*)ppsum);

    dim3 gctx(LL / 128, BB * HH);
    ctx_mma_kernel<<<gctx, 256>>>(probs, (const float*)ppsum, (const float*)pv, (float*)pctx);

    gemm_mma_kernel<true><<<gproj, 256>>>((const float*)pctx, Wd, bd, out, M, DOUT, DV);
}

// round 8
// speedup vs baseline: 1.3368x; 1.0812x over previous
#include <cuda_runtime.h>
#include <cuda_bf16.h>
#include <cstdint>

// Problem constants
#define BB   2
#define LL   2048
#define SS   2048
#define DIN  512
#define DK   512
#define DV   512
#define DOUT 512
#define HH   8
#define HD   64

#define OUT_ELEMS  ((long)BB * LL * DOUT)
#define PROB_ELEMS ((long)BB * HH * (long)LL * (long)SS)

// Scratch (device globals — no runtime allocation allowed)
__device__ float g_qm [BB * HH * (long)LL * DK];    // pre-mixed q per head (64 MB)
__device__ float g_k  [BB * SS * DK];
__device__ float g_v  [BB * SS * DV];
__device__ float g_cb [BB * HH * SS];
__device__ float g_ctx[BB * LL * DV];
__device__ float g_psum[BB * HH * (long)LL * 16];
__device__ float g_probs[BB * HH * (long)LL * SS];

// ---------------------------------------------------------------------------
// tf32 helpers (plain sm_103 target — mma.sync is the tensor path)
// ---------------------------------------------------------------------------
__device__ __forceinline__ float f2tf32(float v) {
    uint32_t r;
    asm("cvt.rna.tf32.f32 %0, %1;" : "=r"(r) : "f"(v));
    return __uint_as_float(r);
}

__device__ __forceinline__ void mma_tf32(float& c0, float& c1, float& c2, float& c3,
                                         float a0, float a1, float a2, float a3,
                                         float b0, float b1) {
    asm volatile(
        "mma.sync.aligned.m16n8k8.row.col.f32.tf32.tf32.f32 "
        "{%0,%1,%2,%3}, {%4,%5,%6,%7}, {%8,%9}, {%0,%1,%2,%3};"
        : "+f"(c0), "+f"(c1), "+f"(c2), "+f"(c3)
        : "r"(__float_as_uint(a0)), "r"(__float_as_uint(a1)),
          "r"(__float_as_uint(a2)), "r"(__float_as_uint(a3)),
          "r"(__float_as_uint(b0)), "r"(__float_as_uint(b1)));
}

#define CP_ASYNC16(dst_u32, src) \
    asm volatile("cp.async.cg.shared.global [%0], [%1], 16;" :: "r"(dst_u32), "l"(src))
#define CP_COMMIT() asm volatile("cp.async.commit_group;" ::: "memory")
#define CP_WAIT2()  asm volatile("cp.async.wait_group 2;" ::: "memory")

#define SKP 20   // padded smem stride for the register-staged kernels

// ---------------------------------------------------------------------------
// Generic tf32 mma GEMM: C[M,N] = A[M,K] * W[N,K]^T (+ bias[n])  (unchanged)
// ---------------------------------------------------------------------------
template <bool HAS_BIAS>
__global__ __launch_bounds__(256, 2)
void gemm_mma_kernel(const float* __restrict__ A,
                     const float* __restrict__ W,
                     const float* __restrict__ bias,
                     float* __restrict__ C,
                     int M, int N, int K) {
    __shared__ float As[2][128][SKP];
    __shared__ float Bs[2][128][SKP];
    __shared__ float bias_s[128];

    const int tid  = threadIdx.x;
    const int wid  = tid >> 5;
    const int lane = tid & 31;
    const int warp_m = wid >> 2;
    const int warp_n = wid & 3;

    const int bm = blockIdx.y * 128;
    const int bn = blockIdx.x * 128;

    const float* Ag = A + (size_t)bm * K;
    const float* Wg = W + (size_t)bn * K;

    if (HAS_BIAS && tid < 128) bias_s[tid] = bias[bn + tid];
    __syncthreads();

    const int gr = tid >> 2;
    const int gc = (tid & 3) * 4;

    float acc[4][4][4];
    #pragma unroll
    for (int i = 0; i < 4; i++)
        #pragma unroll
        for (int j = 0; j < 4; j++)
            #pragma unroll
            for (int t = 0; t < 4; t++) acc[i][j][t] = 0.0f;

    float4 pa[2], pb[2];

    #pragma unroll
    for (int i = 0; i < 2; i++) {
        pa[i] = *(const float4*)(Ag + (size_t)(gr + i * 64) * K + gc);
        pb[i] = *(const float4*)(Wg + (size_t)(gr + i * 64) * K + gc);
    }
    #pragma unroll
    for (int i = 0; i < 2; i++) {
        int r = gr + i * 64;
        float4 ta = make_float4(f2tf32(pa[i].x), f2tf32(pa[i].y), f2tf32(pa[i].z), f2tf32(pa[i].w));
        float4 tb = make_float4(f2tf32(pb[i].x), f2tf32(pb[i].y), f2tf32(pb[i].z), f2tf32(pb[i].w));
        *(float4*)&As[0][r][gc] = ta;
        *(float4*)&Bs[0][r][gc] = tb;
    }
    __syncthreads();

    const int NC = K / 16;
    for (int c = 0; c < NC; c++) {
        if (c + 1 < NC) {
            int kc = (c + 1) * 16;
            #pragma unroll
            for (int i = 0; i < 2; i++) {
                pa[i] = *(const float4*)(Ag + (size_t)(gr + i * 64) * K + kc + gc);
                pb[i] = *(const float4*)(Wg + (size_t)(gr + i * 64) * K + kc + gc);
            }
        }

        const int st = c & 1;
        #pragma unroll
        for (int kk = 0; kk < 2; kk++) {
            const int k0 = kk * 8;
            const int ar = lane >> 2;
            const int ac = lane & 3;
            float a0[4], a1[4], a2[4], a3[4];
            #pragma unroll
            for (int i = 0; i < 4; i++) {
                int m = warp_m * 64 + i * 16;
                a0[i] = As[st][m + ar    ][k0 + ac    ];
                a1[i] = As[st][m + ar + 8][k0 + ac    ];
                a2[i] = As[st][m + ar    ][k0 + ac + 4];
                a3[i] = As[st][m + ar + 8][k0 + ac + 4];
            }
            float b0[4], b1[4];
            #pragma unroll
            for (int j = 0; j < 4; j++) {
                int n = warp_n * 32 + j * 8 + (lane >> 2);
                b0[j] = Bs[st][n][k0 + ac    ];
                b1[j] = Bs[st][n][k0 + ac + 4];
            }
            #pragma unroll
            for (int i = 0; i < 4; i++)
                #pragma unroll
                for (int j = 0; j < 4; j++)
                    mma_tf32(acc[i][j][0], acc[i][j][1], acc[i][j][2], acc[i][j][3],
                             a0[i], a1[i], a2[i], a3[i], b0[j], b1[j]);
        }

        if (c + 1 < NC) {
            __syncthreads();
            const int ns = (c + 1) & 1;
            #pragma unroll
            for (int i = 0; i < 2; i++) {
                int r = gr + i * 64;
                float4 ta = make_float4(f2tf32(pa[i].x), f2tf32(pa[i].y), f2tf32(pa[i].z), f2tf32(pa[i].w));
                float4 tb = make_float4(f2tf32(pb[i].x), f2tf32(pb[i].y), f2tf32(pb[i].z), f2tf32(pb[i].w));
                *(float4*)&As[ns][r][gc] = ta;
                *(float4*)&Bs[ns][r][gc] = tb;
            }
            __syncthreads();
        }
    }

    #pragma unroll
    for (int i = 0; i < 4; i++) {
        int row = bm + warp_m * 64 + i * 16 + (lane >> 2);
        #pragma unroll
        for (int j = 0; j < 4; j++) {
            int col = warp_n * 32 + j * 8 + (lane & 3) * 2;
            float bb0 = HAS_BIAS ? bias_s[col]     : 0.0f;
            float bb1 = HAS_BIAS ? bias_s[col + 1] : 0.0f;
            float2 v0, v1;
            v0.x = acc[i][j][0] + bb0; v0.y = acc[i][j][1] + bb1;
            v1.x = acc[i][j][2] + bb0; v1.y = acc[i][j][3] + bb1;
            *(float2*)(C + (size_t)row * N + bn + col) = v0;
            *(float2*)(C + (size_t)(row + 8) * N + bn + col) = v1;
        }
    }
}

// ---------------------------------------------------------------------------
// q-projection with pre-mixed per-head outputs (unchanged from R7)
// ---------------------------------------------------------------------------
__global__ __launch_bounds__(256, 2)
void qproj_mma_kernel(const float* __restrict__ A,
                      const float* __restrict__ W,
                      const float* __restrict__ mixing,
                      float* __restrict__ qm) {
    __shared__ float As[2][128][SKP];
    __shared__ float Bs[2][128][SKP];
    __shared__ float mix_s[8][128];

    const int tid  = threadIdx.x;
    const int wid  = tid >> 5;
    const int lane = tid & 31;
    const int warp_m = wid >> 2;
    const int warp_n = wid & 3;

    const int bm = blockIdx.y * 128;
    const int bn = blockIdx.x * 128;
    const int K = DIN;

    const float* Ag = A + (size_t)bm * K;
    const float* Wg = W + (size_t)bn * K;

    for (int i = tid; i < 8 * 128; i += 256)
        mix_s[i >> 7][i & 127] = mixing[(i >> 7) * DK + bn + (i & 127)];
    __syncthreads();

    const int gr = tid >> 2;
    const int gc = (tid & 3) * 4;

    float acc[4][4][4];
    #pragma unroll
    for (int i = 0; i < 4; i++)
        #pragma unroll
        for (int j = 0; j < 4; j++)
            #pragma unroll
            for (int t = 0; t < 4; t++) acc[i][j][t] = 0.0f;

    float4 pa[2], pb[2];

    #pragma unroll
    for (int i = 0; i < 2; i++) {
        pa[i] = *(const float4*)(Ag + (size_t)(gr + i * 64) * K + gc);
        pb[i] = *(const float4*)(Wg + (size_t)(gr + i * 64) * K + gc);
    }
    #pragma unroll
    for (int i = 0; i < 2; i++) {
        int r = gr + i * 64;
        float4 ta = make_float4(f2tf32(pa[i].x), f2tf32(pa[i].y), f2tf32(pa[i].z), f2tf32(pa[i].w));
        float4 tb = make_float4(f2tf32(pb[i].x), f2tf32(pb[i].y), f2tf32(pb[i].z), f2tf32(pb[i].w));
        *(float4*)&As[0][r][gc] = ta;
        *(float4*)&Bs[0][r][gc] = tb;
    }
    __syncthreads();

    const int NC = K / 16;
    for (int c = 0; c < NC; c++) {
        if (c + 1 < NC) {
            int kc = (c + 1) * 16;
            #pragma unroll
            for (int i = 0; i < 2; i++) {
                pa[i] = *(const float4*)(Ag + (size_t)(gr + i * 64) * K + kc + gc);
                pb[i] = *(const float4*)(Wg + (size_t)(gr + i * 64) * K + kc + gc);
            }
        }

        const int st = c & 1;
        #pragma unroll
        for (int kk = 0; kk < 2; kk++) {
            const int k0 = kk * 8;
            const int ar = lane >> 2;
            const int ac = lane & 3;
            float a0[4], a1[4], a2[4], a3[4];
            #pragma unroll
            for (int i = 0; i < 4; i++) {
                int m = warp_m * 64 + i * 16;
                a0[i] = As[st][m + ar    ][k0 + ac    ];
                a1[i] = As[st][m + ar + 8][k0 + ac    ];
                a2[i] = As[st][m + ar    ][k0 + ac + 4];
                a3[i] = As[st][m + ar + 8][k0 + ac + 4];
            }
            float b0[4], b1[4];
            #pragma unroll
            for (int j = 0; j < 4; j++) {
                int n = warp_n * 32 + j * 8 + (lane >> 2);
                b0[j] = Bs[st][n][k0 + ac    ];
                b1[j] = Bs[st][n][k0 + ac + 4];
            }
            #pragma unroll
            for (int i = 0; i < 4; i++)
                #pragma unroll
                for (int j = 0; j < 4; j++)
                    mma_tf32(acc[i][j][0], acc[i][j][1], acc[i][j][2], acc[i][j][3],
                             a0[i], a1[i], a2[i], a3[i], b0[j], b1[j]);
        }

        if (c + 1 < NC) {
            __syncthreads();
            const int ns = (c + 1) & 1;
            #pragma unroll
            for (int i = 0; i < 2; i++) {
                int r = gr + i * 64;
                float4 ta = make_float4(f2tf32(pa[i].x), f2tf32(pa[i].y), f2tf32(pa[i].z), f2tf32(pa[i].w));
                float4 tb = make_float4(f2tf32(pb[i].x), f2tf32(pb[i].y), f2tf32(pb[i].z), f2tf32(pb[i].w));
                *(float4*)&As[ns][r][gc] = ta;
                *(float4*)&Bs[ns][r][gc] = tb;
            }
            __syncthreads();
        }
    }

    const int bq = bm >> 11;
    #pragma unroll
    for (int i = 0; i < 4; i++) {
        int row = bm + warp_m * 64 + i * 16 + (lane >> 2);
        int l = row & (LL - 1);
        #pragma unroll
        for (int j = 0; j < 4; j++) {
            int col = warp_n * 32 + j * 8 + (lane & 3) * 2;
            #pragma unroll
            for (int h = 0; h < 8; h++) {
                float m0 = mix_s[h][col], m1 = mix_s[h][col + 1];
                float2 v0, v1;
                v0.x = acc[i][j][0] * m0; v0.y = acc[i][j][1] * m1;
                v1.x = acc[i][j][2] * m0; v1.y = acc[i][j][3] * m1;
                float* base = qm + ((size_t)(bq * HH + h) * LL) * DK + bn + col;
                *(float2*)(base + (size_t)l * DK)       = v0;
                *(float2*)(base + (size_t)(l + 8) * DK) = v1;
            }
        }
    }
}

// ---------------------------------------------------------------------------
// Scores: pure tf32 GEMM, cp.async 3-stage, BK=32 (unchanged mainloop from R7;
// probs stores now streaming __stcs)
// ---------------------------------------------------------------------------
__global__ __launch_bounds__(256, 2)
void scores_mma_kernel(const float* __restrict__ qm,
                       const float* __restrict__ kmat,
                       const float* __restrict__ cb,
                       float* __restrict__ probs,
                       float* __restrict__ psum) {
    extern __shared__ float sm[];
    __shared__ float cb_s[128];
    __shared__ float rs[4][130];

    const int tid  = threadIdx.x;
    const int wid  = tid >> 5;
    const int lane = tid & 31;
    const int warp_m = wid >> 2;
    const int warp_n = wid & 3;

    const int z  = blockIdx.z;
    const int b  = z >> 3;
    const int bm = blockIdx.y * 128;
    const int bn = blockIdx.x * 128;

    const float* Aq = qm   + (size_t)z * LL * DK + (size_t)bm * DK;
    const float* Bk = kmat + (size_t)b * SS * DK + (size_t)bn * DK;

    if (tid < 128) cb_s[tid] = cb[(size_t)z * SS + bn + tid];

    const uint32_t sbase = (uint32_t)__cvta_generic_to_shared(sm);

    auto issue = [&](int cidx) {
        const uint32_t st_off = (uint32_t)(cidx % 3) * 8192u * 4u;
        const int kc = cidx * 32;
        #pragma unroll
        for (int i = 0; i < 4; i++) {
            int idx = tid + i * 256;
            int r   = idx >> 3;
            int gcf = (idx & 7) * 4;
            int sc  = gcf ^ ((r & 7) << 2);
            uint32_t da = sbase + st_off + (uint32_t)(r * 32 + sc) * 4u;
            CP_ASYNC16(da,          Aq + (size_t)r * DK + kc + gcf);
            CP_ASYNC16(da + 16384u, Bk + (size_t)r * DK + kc + gcf);
        }
    };

    float acc[4][4][4];
    #pragma unroll
    for (int i = 0; i < 4; i++)
        #pragma unroll
        for (int j = 0; j < 4; j++)
            #pragma unroll
            for (int t = 0; t < 4; t++) acc[i][j][t] = 0.0f;

    const int NC = DK / 32;
    issue(0); CP_COMMIT();
    issue(1); CP_COMMIT();

    const int ar = lane >> 2;
    const int ac = lane & 3;

    for (int c = 0; c < NC; c++) {
        if (c + 2 < NC) issue(c + 2);
        CP_COMMIT();
        CP_WAIT2();
        __syncthreads();

        const float* As = sm + (c % 3) * 8192;
        const float* Bs = As + 4096;

        #pragma unroll
        for (int kk = 0; kk < 4; kk++) {
            const int k0 = kk * 8;
            const int sc0 = (k0 + ac)     ^ (ar << 2);
            const int sc1 = (k0 + ac + 4) ^ (ar << 2);
            float a0[4], a1[4], a2[4], a3[4];
            #pragma unroll
            for (int i = 0; i < 4; i++) {
                int m = warp_m * 64 + i * 16;
                a0[i] = As[(m + ar    ) * 32 + sc0];
                a1[i] = As[(m + ar + 8) * 32 + sc0];
                a2[i] = As[(m + ar    ) * 32 + sc1];
                a3[i] = As[(m + ar + 8) * 32 + sc1];
            }
            float b0[4], b1[4];
            #pragma unroll
            for (int j = 0; j < 4; j++) {
                int n = warp_n * 32 + j * 8 + ar;
                b0[j] = Bs[n * 32 + sc0];
                b1[j] = Bs[n * 32 + sc1];
            }
            #pragma unroll
            for (int i = 0; i < 4; i++)
                #pragma unroll
                for (int j = 0; j < 4; j++)
                    mma_tf32(acc[i][j][0], acc[i][j][1], acc[i][j][2], acc[i][j][3],
                             a0[i], a1[i], a2[i], a3[i], b0[j], b1[j]);
        }
        __syncthreads();
    }

    const size_t rowbase = (size_t)z * LL;
    float rsum[4][2];
    #pragma unroll
    for (int i = 0; i < 4; i++) { rsum[i][0] = 0.0f; rsum[i][1] = 0.0f; }

    #pragma unroll
    for (int i = 0; i < 4; i++) {
        int row = bm + warp_m * 64 + i * 16 + ar;
        #pragma unroll
        for (int j = 0; j < 4; j++) {
            int col = warp_n * 32 + j * 8 + (lane & 3) * 2;
            float cb0 = cb_s[col], cb1 = cb_s[col + 1];
            float2 v0, v1;
            v0.x = __expf((acc[i][j][0] + cb0) * 0.125f);
            v0.y = __expf((acc[i][j][1] + cb1) * 0.125f);
            v1.x = __expf((acc[i][j][2] + cb0) * 0.125f);
            v1.y = __expf((acc[i][j][3] + cb1) * 0.125f);
            rsum[i][0] += v0.x + v0.y;
            rsum[i][1] += v1.x + v1.y;
            __stcs((float2*)(probs + (rowbase + row    ) * SS + bn + col), v0);
            __stcs((float2*)(probs + (rowbase + row + 8) * SS + bn + col), v1);
        }
    }
    #pragma unroll
    for (int i = 0; i < 4; i++) {
        rsum[i][0] += __shfl_xor_sync(0xffffffffu, rsum[i][0], 1);
        rsum[i][0] += __shfl_xor_sync(0xffffffffu, rsum[i][0], 2);
        rsum[i][1] += __shfl_xor_sync(0xffffffffu, rsum[i][1], 1);
        rsum[i][1] += __shfl_xor_sync(0xffffffffu, rsum[i][1], 2);
    }
    if ((lane & 3) == 0) {
        #pragma unroll
        for (int i = 0; i < 4; i++) {
            int r = warp_m * 64 + i * 16 + ar;
            rs[warp_n][r]     = rsum[i][0];
            rs[warp_n][r + 8] = rsum[i][1];
        }
    }
    __syncthreads();
    if (tid < 128) {
        float s = rs[0][tid] + rs[1][tid] + rs[2][tid] + rs[3][tid];
        psum[(rowbase + bm + tid) * 16 + blockIdx.x] = s;
    }
}

// ---------------------------------------------------------------------------
// ctx via tf32 mma, cp.async 3-stage, BK=32, fused normalization.
// Per (b,h): C[2048x64] = (e*inv)[2048x2048] @ Vh[2048x64]; normalized probs
// written back with streaming stores. grid = (L/128, B*H), 256 threads.
// Stage layout (floats): P tile 128x32 swizzled (4096) + V tile 32 rows x
// stride 72 (2304) = 6400 per stage, 3 stages = 76800 B dynamic smem.
// ---------------------------------------------------------------------------
#define CTX_STAGE 6400

__global__ __launch_bounds__(256, 2)
void ctx_mma_kernel(float* __restrict__ probs,
                    const float* __restrict__ psum,
                    const float* __restrict__ v,
                    float* __restrict__ ctx) {
    extern __shared__ float sm[];
    __shared__ float invs[128];

    const int tid  = threadIdx.x;
    const int wid  = tid >> 5;
    const int lane = tid & 31;
    const int warp_m = wid >> 2;
    const int warp_n = wid & 3;

    const int z  = blockIdx.y;
    const int b  = z >> 3;
    const int h  = z & 7;
    const int bm = blockIdx.x * 128;

    float* P = probs + ((size_t)z * LL + bm) * SS;
    const float* V = v + (size_t)b * SS * DV + h * HD;

    if (tid < 128) {
        const float* pp = psum + ((size_t)z * LL + bm + tid) * 16;
        float4 s0 = *(const float4*)(pp + 0);
        float4 s1 = *(const float4*)(pp + 4);
        float4 s2 = *(const float4*)(pp + 8);
        float4 s3 = *(const float4*)(pp + 12);
        float s = ((s0.x + s0.y) + (s0.z + s0.w)) + ((s1.x + s1.y) + (s1.z + s1.w))
                + ((s2.x + s2.y) + (s2.z + s2.w)) + ((s3.x + s3.y) + (s3.z + s3.w));
        invs[tid] = 1.0f / s;
    }
    __syncthreads();

    const uint32_t sbase = (uint32_t)__cvta_generic_to_shared(sm);

    auto issue = [&](int cidx) {
        const uint32_t st = (uint32_t)(cidx % 3) * (CTX_STAGE * 4u);
        const int kc = cidx * 32;
        #pragma unroll
        for (int i = 0; i < 4; i++) {
            int idx = tid + i * 256;
            int r   = idx >> 3;
            int gcf = (idx & 7) * 4;
            int sc  = gcf ^ ((r & 7) << 2);
            CP_ASYNC16(sbase + st + (uint32_t)(r * 32 + sc) * 4u,
                       P + (size_t)r * SS + kc + gcf);
        }
        #pragma unroll
        for (int i = 0; i < 2; i++) {
            int idx = tid + i * 256;   // 0..511
            int vr  = idx >> 4;        // 0..31
            int vc  = (idx & 15) * 4;  // 0..60
            CP_ASYNC16(sbase + st + (uint32_t)(4096 + vr * 72 + vc) * 4u,
                       V + (size_t)(kc + vr) * DV + vc);
        }
    };

    const int ar = lane >> 2;
    const int ac = lane & 3;

    // per-thread row inverses: fragment rows (fixed across chunks)
    float ivA[8];
    #pragma unroll
    for (int i = 0; i < 4; i++) {
        ivA[2 * i]     = invs[warp_m * 64 + i * 16 + ar];
        ivA[2 * i + 1] = invs[warp_m * 64 + i * 16 + ar + 8];
    }
    // write-back row inverses
    float ivW[4];
    #pragma unroll
    for (int i = 0; i < 4; i++) ivW[i] = invs[(tid + i * 256) >> 3];

    float acc[4][2][4];
    #pragma unroll
    for (int i = 0; i < 4; i++)
        #pragma unroll
        for (int j = 0; j < 2; j++)
            #pragma unroll
            for (int t = 0; t < 4; t++) acc[i][j][t] = 0.0f;

    const int NC = SS / 32;   // 64 chunks
    issue(0); CP_COMMIT();
    issue(1); CP_COMMIT();

    for (int c = 0; c < NC; c++) {
        if (c + 2 < NC) issue(c + 2);
        CP_COMMIT();
        CP_WAIT2();
        __syncthreads();

        const float* Ps = sm + (c % 3) * CTX_STAGE;
        const float* Vs = Ps + 4096;
        const int kc = c * 32;

        // write normalized probs for this chunk (streaming; CTA-exclusive rows)
        #pragma unroll
        for (int i = 0; i < 4; i++) {
            int idx = tid + i * 256;
            int r   = idx >> 3;
            int gcf = (idx & 7) * 4;
            int sc  = gcf ^ ((r & 7) << 2);
            float4 e = *(const float4*)&Ps[r * 32 + sc];
            float iv = ivW[i];
            float4 nv = make_float4(e.x * iv, e.y * iv, e.z * iv, e.w * iv);
            __stcs((float4*)(P + (size_t)r * SS + kc + gcf), nv);
        }

        #pragma unroll
        for (int kk = 0; kk < 4; kk++) {
            const int k0 = kk * 8;
            const int sc0 = (k0 + ac)     ^ (ar << 2);
            const int sc1 = (k0 + ac + 4) ^ (ar << 2);
            float a0[4], a1[4], a2[4], a3[4];
            #pragma unroll
            for (int i = 0; i < 4; i++) {
                int m = warp_m * 64 + i * 16;
                a0[i] = Ps[(m + ar    ) * 32 + sc0] * ivA[2 * i];
                a1[i] = Ps[(m + ar + 8) * 32 + sc0] * ivA[2 * i + 1];
                a2[i] = Ps[(m + ar    ) * 32 + sc1] * ivA[2 * i];
                a3[i] = Ps[(m + ar + 8) * 32 + sc1] * ivA[2 * i + 1];
            }
            float b0[2], b1[2];
            #pragma unroll
            for (int j = 0; j < 2; j++) {
                int n = warp_n * 16 + j * 8 + ar;
                b0[j] = Vs[(k0 + ac) * 72 + n];
                b1[j] = Vs[(k0 + ac + 4) * 72 + n];
            }
            #pragma unroll
            for (int i = 0; i < 4; i++)
                #pragma unroll
                for (int j = 0; j < 2; j++)
                    mma_tf32(acc[i][j][0], acc[i][j][1], acc[i][j][2], acc[i][j][3],
                             a0[i], a1[i], a2[i], a3[i], b0[j], b1[j]);
        }
        __syncthreads();
    }

    #pragma unroll
    for (int i = 0; i < 4; i++) {
        int row = bm + warp_m * 64 + i * 16 + ar;
        #pragma unroll
        for (int j = 0; j < 2; j++) {
            int col = warp_n * 16 + j * 8 + ac * 2;
            float2 v0, v1;
            v0.x = acc[i][j][0]; v0.y = acc[i][j][1];
            v1.x = acc[i][j][2]; v1.y = acc[i][j][3];
            *(float2*)(ctx + (size_t)(b * LL + row) * DV + h * HD + col) = v0;
            *(float2*)(ctx + (size_t)(b * LL + row + 8) * DV + h * HD + col) = v1;
        }
    }
}

// ---------------------------------------------------------------------------
// cb kernel (unchanged)
// ---------------------------------------------------------------------------
__global__ void cb_kernel(const float* __restrict__ keys,
                          const float* __restrict__ Wcb,
                          float* __restrict__ cb) {
    const int bs = blockIdx.x;
    const int b  = bs / SS;
    const int s  = bs % SS;
    __shared__ float krow[DIN];
    const int tid = threadIdx.x;
    for (int i = tid; i < DIN; i += 256) krow[i] = keys[(size_t)bs * DIN + i];
    __syncthreads();
    const int w    = tid >> 5;
    const int lane = tid & 31;
    float sum = 0.0f;
    #pragma unroll 4
    for (int i = lane; i < DIN; i += 32) sum += krow[i] * Wcb[w * DIN + i];
    #pragma unroll
    for (int o = 16; o > 0; o >>= 1) sum += __shfl_down_sync(0xffffffffu, sum, o);
    if (lane == 0) cb[(size_t)(b * HH + w) * SS + s] = sum;
}

// ---------------------------------------------------------------------------
extern "C" void kernel_launch(void* const* d_in, const int* in_sizes, int n_in,
                              void* d_out, int out_size) {
    const float* queries = (const float*)d_in[0];
    const float* keys    = (const float*)d_in[1];
    const float* values  = (const float*)d_in[2];
    const float* Wq      = (const float*)d_in[4];
    const float* Wk      = (const float*)d_in[5];
    const float* Wv      = (const float*)d_in[6];
    const float* bv      = (const float*)d_in[7];
    const float* Wcb     = (const float*)d_in[8];
    const float* mixing  = (const float*)d_in[9];
    const float* Wd      = (const float*)d_in[10];
    const float* bd      = (const float*)d_in[11];

    float* out = (float*)d_out;

    void *pqm, *pk, *pv, *pcb, *pctx, *ppsum, *pprobs;
    cudaGetSymbolAddress(&pqm,   g_qm);
    cudaGetSymbolAddress(&pk,    g_k);
    cudaGetSymbolAddress(&pv,    g_v);
    cudaGetSymbolAddress(&pcb,   g_cb);
    cudaGetSymbolAddress(&pctx,  g_ctx);
    cudaGetSymbolAddress(&ppsum, g_psum);
    cudaGetSymbolAddress(&pprobs, g_probs);

    float* probs;
    if ((long)out_size >= OUT_ELEMS + PROB_ELEMS) probs = out + OUT_ELEMS;
    else                                           probs = (float*)pprobs;

    const int SC_SMEM  = 3 * 8192 * 4;        // 96 KB
    const int CTX_SMEM = 3 * CTX_STAGE * 4;   // 76.8 KB
    cudaFuncSetAttribute(scores_mma_kernel,
                         cudaFuncAttributeMaxDynamicSharedMemorySize, SC_SMEM);
    cudaFuncSetAttribute(ctx_mma_kernel,
                         cudaFuncAttributeMaxDynamicSharedMemorySize, CTX_SMEM);

    const int M = BB * LL;

    cb_kernel<<<BB * SS, 256>>>(keys, Wcb, (float*)pcb);

    dim3 gproj(DOUT / 128, M / 128);
    qproj_mma_kernel<<<gproj, 256>>>(queries, Wq, mixing, (float*)pqm);
    gemm_mma_kernel<false><<<gproj, 256>>>(keys,   Wk, nullptr, (float*)pk, M, DK, DIN);
    gemm_mma_kernel<true ><<<gproj, 256>>>(values, Wv, bv,      (float*)pv, M, DV, DIN);

    dim3 gsc(SS / 128, LL / 128, BB * HH);
    scores_mma_kernel<<<gsc, 256, SC_SMEM>>>((const float*)pqm, (const float*)pk,
                                             (const float*)pcb, probs, (float*)ppsum);

    dim3 gctx(LL / 128, BB * HH);
    ctx_mma_kernel<<<gctx, 256, CTX_SMEM>>>(probs, (const float*)ppsum,
                                            (const float*)pv, (float*)pctx);

    gemm_mma_kernel<true><<<gproj, 256>>>((const float*)pctx, Wd, bd, out, M, DOUT, DV);
}

// round 10
// speedup vs baseline: 1.4302x; 1.0699x over previous
#include <cuda_runtime.h>
#include <cuda_bf16.h>
#include <cstdint>

// Problem constants
#define BB   2
#define LL   2048
#define SS   2048
#define DIN  512
#define DK   512
#define DV   512
#define DOUT 512
#define HH   8
#define HD   64

#define OUT_ELEMS  ((long)BB * LL * DOUT)
#define PROB_ELEMS ((long)BB * HH * (long)LL * (long)SS)

// Scratch (device globals — no runtime allocation allowed)
__device__ float g_q  [BB * LL * DK];
__device__ float g_k  [BB * SS * DK];
__device__ float g_v  [BB * SS * DV];
__device__ float g_cb [BB * HH * SS];
__device__ float g_ctx[BB * LL * DV];
__device__ float g_psum[BB * HH * (long)LL * 16];
__device__ float g_probs[BB * HH * (long)LL * SS];

// ---------------------------------------------------------------------------
// tf32 helpers (plain sm_103 target — mma.sync is the tensor path)
// ---------------------------------------------------------------------------
__device__ __forceinline__ void mma_tf32(float& c0, float& c1, float& c2, float& c3,
                                         float a0, float a1, float a2, float a3,
                                         float b0, float b1) {
    asm volatile(
        "mma.sync.aligned.m16n8k8.row.col.f32.tf32.tf32.f32 "
        "{%0,%1,%2,%3}, {%4,%5,%6,%7}, {%8,%9}, {%0,%1,%2,%3};"
        : "+f"(c0), "+f"(c1), "+f"(c2), "+f"(c3)
        : "r"(__float_as_uint(a0)), "r"(__float_as_uint(a1)),
          "r"(__float_as_uint(a2)), "r"(__float_as_uint(a3)),
          "r"(__float_as_uint(b0)), "r"(__float_as_uint(b1)));
}

#define CP_ASYNC16(dst_u32, src) \
    asm volatile("cp.async.cg.shared.global [%0], [%1], 16;" :: "r"(dst_u32), "l"(src))
#define CP_COMMIT() asm volatile("cp.async.commit_group;" ::: "memory")
#define CP_WAIT2()  asm volatile("cp.async.wait_group 2;" ::: "memory")

// ---------------------------------------------------------------------------
// Pipelined tf32 GEMM: C[M,N] = A[M,K] * W[N,K]^T (+ bias[n])
// cp.async 3-stage, BK=32, XOR-swizzled 128x32 tiles, 8 warps (2m x 4n).
// grid = (N/128, M/128), 256 threads, 96KB dynamic smem.
// ---------------------------------------------------------------------------
template <bool HAS_BIAS>
__global__ __launch_bounds__(256, 2)
void gemm_cp_kernel(const float* __restrict__ A,
                    const float* __restrict__ W,
                    const float* __restrict__ bias,
                    float* __restrict__ C,
                    int M, int N, int K) {
    extern __shared__ float sm[];
    __shared__ float bias_s[128];

    const int tid  = threadIdx.x;
    const int wid  = tid >> 5;
    const int lane = tid & 31;
    const int warp_m = wid >> 2;
    const int warp_n = wid & 3;

    const int bm = blockIdx.y * 128;
    const int bn = blockIdx.x * 128;

    const float* Ag = A + (size_t)bm * K;
    const float* Wg = W + (size_t)bn * K;

    if (HAS_BIAS && tid < 128) bias_s[tid] = bias[bn + tid];

    const uint32_t sbase = (uint32_t)__cvta_generic_to_shared(sm);

    auto issue = [&](int cidx) {
        const uint32_t st_off = (uint32_t)(cidx % 3) * 8192u * 4u;
        const int kc = cidx * 32;
        #pragma unroll
        for (int i = 0; i < 4; i++) {
            int idx = tid + i * 256;
            int r   = idx >> 3;
            int gcf = (idx & 7) * 4;
            int sc  = gcf ^ ((r & 7) << 2);
            uint32_t da = sbase + st_off + (uint32_t)(r * 32 + sc) * 4u;
            CP_ASYNC16(da,          Ag + (size_t)r * K + kc + gcf);
            CP_ASYNC16(da + 16384u, Wg + (size_t)r * K + kc + gcf);
        }
    };

    float acc[4][4][4];
    #pragma unroll
    for (int i = 0; i < 4; i++)
        #pragma unroll
        for (int j = 0; j < 4; j++)
            #pragma unroll
            for (int t = 0; t < 4; t++) acc[i][j][t] = 0.0f;

    const int NC = K / 32;
    issue(0); CP_COMMIT();
    issue(1); CP_COMMIT();

    const int ar = lane >> 2;
    const int ac = lane & 3;

    for (int c = 0; c < NC; c++) {
        if (c + 2 < NC) issue(c + 2);
        CP_COMMIT();
        CP_WAIT2();
        __syncthreads();

        const float* As = sm + (c % 3) * 8192;
        const float* Bs = As + 4096;

        #pragma unroll
        for (int kk = 0; kk < 4; kk++) {
            const int k0 = kk * 8;
            const int sc0 = (k0 + ac)     ^ (ar << 2);
            const int sc1 = (k0 + ac + 4) ^ (ar << 2);
            float a0[4], a1[4], a2[4], a3[4];
            #pragma unroll
            for (int i = 0; i < 4; i++) {
                int m = warp_m * 64 + i * 16;
                a0[i] = As[(m + ar    ) * 32 + sc0];
                a1[i] = As[(m + ar + 8) * 32 + sc0];
                a2[i] = As[(m + ar    ) * 32 + sc1];
                a3[i] = As[(m + ar + 8) * 32 + sc1];
            }
            float b0[4], b1[4];
            #pragma unroll
            for (int j = 0; j < 4; j++) {
                int n = warp_n * 32 + j * 8 + ar;
                b0[j] = Bs[n * 32 + sc0];
                b1[j] = Bs[n * 32 + sc1];
            }
            #pragma unroll
            for (int i = 0; i < 4; i++)
                #pragma unroll
                for (int j = 0; j < 4; j++)
                    mma_tf32(acc[i][j][0], acc[i][j][1], acc[i][j][2], acc[i][j][3],
                             a0[i], a1[i], a2[i], a3[i], b0[j], b1[j]);
        }
        __syncthreads();
    }

    #pragma unroll
    for (int i = 0; i < 4; i++) {
        int row = bm + warp_m * 64 + i * 16 + ar;
        #pragma unroll
        for (int j = 0; j < 4; j++) {
            int col = warp_n * 32 + j * 8 + ac * 2;
            float bb0 = HAS_BIAS ? bias_s[col]     : 0.0f;
            float bb1 = HAS_BIAS ? bias_s[col + 1] : 0.0f;
            float2 v0, v1;
            v0.x = acc[i][j][0] + bb0; v0.y = acc[i][j][1] + bb1;
            v1.x = acc[i][j][2] + bb0; v1.y = acc[i][j][3] + bb1;
            *(float2*)(C + (size_t)row * N + bn + col) = v0;
            *(float2*)(C + (size_t)(row + 8) * N + bn + col) = v1;
        }
    }
}

// ---------------------------------------------------------------------------
// Scores: tf32 GEMM, cp.async 3-stage, BK=32; mixing folded into A-fragment
// loads (fp32 product, truncated at mma — identical numerics to the old
// pre-mixed-qm path):
//   e[z,l,s] = exp((sum_k q[l,k]*mix[h,k]*kmat[s,k] + cb[z,s]) / 8) -> probs
//   psum[z,l,cta_n] = partial row sums (deterministic)
// grid = (S/128, L/128, B*H), 256 threads, 96KB dynamic smem.
// ---------------------------------------------------------------------------
__global__ __launch_bounds__(256, 2)
void scores_mma_kernel(const float* __restrict__ q,
                       const float* __restrict__ kmat,
                       const float* __restrict__ mixing,
                       const float* __restrict__ cb,
                       float* __restrict__ probs,
                       float* __restrict__ psum) {
    extern __shared__ float sm[];
    __shared__ float mix_s[DK];
    __shared__ float cb_s[128];
    __shared__ float rs[4][130];

    const int tid  = threadIdx.x;
    const int wid  = tid >> 5;
    const int lane = tid & 31;
    const int warp_m = wid >> 2;
    const int warp_n = wid & 3;

    const int z  = blockIdx.z;
    const int b  = z >> 3;
    const int h  = z & 7;
    const int bm = blockIdx.y * 128;
    const int bn = blockIdx.x * 128;

    const float* Aq = q    + (size_t)b * LL * DK + (size_t)bm * DK;
    const float* Bk = kmat + (size_t)b * SS * DK + (size_t)bn * DK;

    for (int i = tid; i < DK; i += 256) mix_s[i] = mixing[h * DK + i];
    if (tid < 128) cb_s[tid] = cb[(size_t)z * SS + bn + tid];

    const uint32_t sbase = (uint32_t)__cvta_generic_to_shared(sm);

    auto issue = [&](int cidx) {
        const uint32_t st_off = (uint32_t)(cidx % 3) * 8192u * 4u;
        const int kc = cidx * 32;
        #pragma unroll
        for (int i = 0; i < 4; i++) {
            int idx = tid + i * 256;
            int r   = idx >> 3;
            int gcf = (idx & 7) * 4;
            int sc  = gcf ^ ((r & 7) << 2);
            uint32_t da = sbase + st_off + (uint32_t)(r * 32 + sc) * 4u;
            CP_ASYNC16(da,          Aq + (size_t)r * DK + kc + gcf);
            CP_ASYNC16(da + 16384u, Bk + (size_t)r * DK + kc + gcf);
        }
    };

    float acc[4][4][4];
    #pragma unroll
    for (int i = 0; i < 4; i++)
        #pragma unroll
        for (int j = 0; j < 4; j++)
            #pragma unroll
            for (int t = 0; t < 4; t++) acc[i][j][t] = 0.0f;

    const int NC = DK / 32;
    issue(0); CP_COMMIT();
    issue(1); CP_COMMIT();
    __syncthreads();   // mix_s/cb_s visible before mainloop fragment use

    const int ar = lane >> 2;
    const int ac = lane & 3;

    for (int c = 0; c < NC; c++) {
        if (c + 2 < NC) issue(c + 2);
        CP_COMMIT();
        CP_WAIT2();
        __syncthreads();

        const float* As = sm + (c % 3) * 8192;
        const float* Bs = As + 4096;
        const int kc = c * 32;

        #pragma unroll
        for (int kk = 0; kk < 4; kk++) {
            const int k0 = kk * 8;
            const int sc0 = (k0 + ac)     ^ (ar << 2);
            const int sc1 = (k0 + ac + 4) ^ (ar << 2);
            const float mv0 = mix_s[kc + k0 + ac];
            const float mv1 = mix_s[kc + k0 + ac + 4];
            float a0[4], a1[4], a2[4], a3[4];
            #pragma unroll
            for (int i = 0; i < 4; i++) {
                int m = warp_m * 64 + i * 16;
                a0[i] = As[(m + ar    ) * 32 + sc0] * mv0;
                a1[i] = As[(m + ar + 8) * 32 + sc0] * mv0;
                a2[i] = As[(m + ar    ) * 32 + sc1] * mv1;
                a3[i] = As[(m + ar + 8) * 32 + sc1] * mv1;
            }
            float b0[4], b1[4];
            #pragma unroll
            for (int j = 0; j < 4; j++) {
                int n = warp_n * 32 + j * 8 + ar;
                b0[j] = Bs[n * 32 + sc0];
                b1[j] = Bs[n * 32 + sc1];
            }
            #pragma unroll
            for (int i = 0; i < 4; i++)
                #pragma unroll
                for (int j = 0; j < 4; j++)
                    mma_tf32(acc[i][j][0], acc[i][j][1], acc[i][j][2], acc[i][j][3],
                             a0[i], a1[i], a2[i], a3[i], b0[j], b1[j]);
        }
        __syncthreads();
    }

    const size_t rowbase = (size_t)z * LL;
    float rsum[4][2];
    #pragma unroll
    for (int i = 0; i < 4; i++) { rsum[i][0] = 0.0f; rsum[i][1] = 0.0f; }

    #pragma unroll
    for (int i = 0; i < 4; i++) {
        int row = bm + warp_m * 64 + i * 16 + ar;
        #pragma unroll
        for (int j = 0; j < 4; j++) {
            int col = warp_n * 32 + j * 8 + ac * 2;
            float cb0 = cb_s[col], cb1 = cb_s[col + 1];
            float2 v0, v1;
            v0.x = __expf((acc[i][j][0] + cb0) * 0.125f);
            v0.y = __expf((acc[i][j][1] + cb1) * 0.125f);
            v1.x = __expf((acc[i][j][2] + cb0) * 0.125f);
            v1.y = __expf((acc[i][j][3] + cb1) * 0.125f);
            rsum[i][0] += v0.x + v0.y;
            rsum[i][1] += v1.x + v1.y;
            __stcs((float2*)(probs + (rowbase + row    ) * SS + bn + col), v0);
            __stcs((float2*)(probs + (rowbase + row + 8) * SS + bn + col), v1);
        }
    }
    #pragma unroll
    for (int i = 0; i < 4; i++) {
        rsum[i][0] += __shfl_xor_sync(0xffffffffu, rsum[i][0], 1);
        rsum[i][0] += __shfl_xor_sync(0xffffffffu, rsum[i][0], 2);
        rsum[i][1] += __shfl_xor_sync(0xffffffffu, rsum[i][1], 1);
        rsum[i][1] += __shfl_xor_sync(0xffffffffu, rsum[i][1], 2);
    }
    if ((lane & 3) == 0) {
        #pragma unroll
        for (int i = 0; i < 4; i++) {
            int r = warp_m * 64 + i * 16 + ar;
            rs[warp_n][r]     = rsum[i][0];
            rs[warp_n][r + 8] = rsum[i][1];
        }
    }
    __syncthreads();
    if (tid < 128) {
        float s = rs[0][tid] + rs[1][tid] + rs[2][tid] + rs[3][tid];
        psum[(rowbase + bm + tid) * 16 + blockIdx.x] = s;
    }
}

// ---------------------------------------------------------------------------
// ctx via tf32 mma, cp.async 3-stage, BK=32, fused normalization (unchanged
// from R8 — passing).
// ---------------------------------------------------------------------------
#define CTX_STAGE 6400

__global__ __launch_bounds__(256, 2)
void ctx_mma_kernel(float* __restrict__ probs,
                    const float* __restrict__ psum,
                    const float* __restrict__ v,
                    float* __restrict__ ctx) {
    extern __shared__ float sm[];
    __shared__ float invs[128];

    const int tid  = threadIdx.x;
    const int wid  = tid >> 5;
    const int lane = tid & 31;
    const int warp_m = wid >> 2;
    const int warp_n = wid & 3;

    const int z  = blockIdx.y;
    const int b  = z >> 3;
    const int h  = z & 7;
    const int bm = blockIdx.x * 128;

    float* P = probs + ((size_t)z * LL + bm) * SS;
    const float* V = v + (size_t)b * SS * DV + h * HD;

    if (tid < 128) {
        const float* pp = psum + ((size_t)z * LL + bm + tid) * 16;
        float4 s0 = *(const float4*)(pp + 0);
        float4 s1 = *(const float4*)(pp + 4);
        float4 s2 = *(const float4*)(pp + 8);
        float4 s3 = *(const float4*)(pp + 12);
        float s = ((s0.x + s0.y) + (s0.z + s0.w)) + ((s1.x + s1.y) + (s1.z + s1.w))
                + ((s2.x + s2.y) + (s2.z + s2.w)) + ((s3.x + s3.y) + (s3.z + s3.w));
        invs[tid] = 1.0f / s;
    }
    __syncthreads();

    const uint32_t sbase = (uint32_t)__cvta_generic_to_shared(sm);

    auto issue = [&](int cidx) {
        const uint32_t st = (uint32_t)(cidx % 3) * (CTX_STAGE * 4u);
        const int kc = cidx * 32;
        #pragma unroll
        for (int i = 0; i < 4; i++) {
            int idx = tid + i * 256;
            int r   = idx >> 3;
            int gcf = (idx & 7) * 4;
            int sc  = gcf ^ ((r & 7) << 2);
            CP_ASYNC16(sbase + st + (uint32_t)(r * 32 + sc) * 4u,
                       P + (size_t)r * SS + kc + gcf);
        }
        #pragma unroll
        for (int i = 0; i < 2; i++) {
            int idx = tid + i * 256;
            int vr  = idx >> 4;
            int vc  = (idx & 15) * 4;
            CP_ASYNC16(sbase + st + (uint32_t)(4096 + vr * 72 + vc) * 4u,
                       V + (size_t)(kc + vr) * DV + vc);
        }
    };

    const int ar = lane >> 2;
    const int ac = lane & 3;

    float ivA[8];
    #pragma unroll
    for (int i = 0; i < 4; i++) {
        ivA[2 * i]     = invs[warp_m * 64 + i * 16 + ar];
        ivA[2 * i + 1] = invs[warp_m * 64 + i * 16 + ar + 8];
    }
    float ivW[4];
    #pragma unroll
    for (int i = 0; i < 4; i++) ivW[i] = invs[(tid + i * 256) >> 3];

    float acc[4][2][4];
    #pragma unroll
    for (int i = 0; i < 4; i++)
        #pragma unroll
        for (int j = 0; j < 2; j++)
            #pragma unroll
            for (int t = 0; t < 4; t++) acc[i][j][t] = 0.0f;

    const int NC = SS / 32;
    issue(0); CP_COMMIT();
    issue(1); CP_COMMIT();

    for (int c = 0; c < NC; c++) {
        if (c + 2 < NC) issue(c + 2);
        CP_COMMIT();
        CP_WAIT2();
        __syncthreads();

        const float* Ps = sm + (c % 3) * CTX_STAGE;
        const float* Vs = Ps + 4096;
        const int kc = c * 32;

        #pragma unroll
        for (int i = 0; i < 4; i++) {
            int idx = tid + i * 256;
            int r   = idx >> 3;
            int gcf = (idx & 7) * 4;
            int sc  = gcf ^ ((r & 7) << 2);
            float4 e = *(const float4*)&Ps[r * 32 + sc];
            float iv = ivW[i];
            float4 nv = make_float4(e.x * iv, e.y * iv, e.z * iv, e.w * iv);
            __stcs((float4*)(P + (size_t)r * SS + kc + gcf), nv);
        }

        #pragma unroll
        for (int kk = 0; kk < 4; kk++) {
            const int k0 = kk * 8;
            const int sc0 = (k0 + ac)     ^ (ar << 2);
            const int sc1 = (k0 + ac + 4) ^ (ar << 2);
            float a0[4], a1[4], a2[4], a3[4];
            #pragma unroll
            for (int i = 0; i < 4; i++) {
                int m = warp_m * 64 + i * 16;
                a0[i] = Ps[(m + ar    ) * 32 + sc0] * ivA[2 * i];
                a1[i] = Ps[(m + ar + 8) * 32 + sc0] * ivA[2 * i + 1];
                a2[i] = Ps[(m + ar    ) * 32 + sc1] * ivA[2 * i];
                a3[i] = Ps[(m + ar + 8) * 32 + sc1] * ivA[2 * i + 1];
            }
            float b0[2], b1[2];
            #pragma unroll
            for (int j = 0; j < 2; j++) {
                int n = warp_n * 16 + j * 8 + ar;
                b0[j] = Vs[(k0 + ac) * 72 + n];
                b1[j] = Vs[(k0 + ac + 4) * 72 + n];
            }
            #pragma unroll
            for (int i = 0; i < 4; i++)
                #pragma unroll
                for (int j = 0; j < 2; j++)
                    mma_tf32(acc[i][j][0], acc[i][j][1], acc[i][j][2], acc[i][j][3],
                             a0[i], a1[i], a2[i], a3[i], b0[j], b1[j]);
        }
        __syncthreads();
    }

    #pragma unroll
    for (int i = 0; i < 4; i++) {
        int row = bm + warp_m * 64 + i * 16 + ar;
        #pragma unroll
        for (int j = 0; j < 2; j++) {
            int col = warp_n * 16 + j * 8 + ac * 2;
            float2 v0, v1;
            v0.x = acc[i][j][0]; v0.y = acc[i][j][1];
            v1.x = acc[i][j][2]; v1.y = acc[i][j][3];
            *(float2*)(ctx + (size_t)(b * LL + row) * DV + h * HD + col) = v0;
            *(float2*)(ctx + (size_t)(b * LL + row + 8) * DV + h * HD + col) = v1;
        }
    }
}

// ---------------------------------------------------------------------------
// cb kernel (unchanged)
// ---------------------------------------------------------------------------
__global__ void cb_kernel(const float* __restrict__ keys,
                          const float* __restrict__ Wcb,
                          float* __restrict__ cb) {
    const int bs = blockIdx.x;
    const int b  = bs / SS;
    const int s  = bs % SS;
    __shared__ float krow[DIN];
    const int tid = threadIdx.x;
    for (int i = tid; i < DIN; i += 256) krow[i] = keys[(size_t)bs * DIN + i];
    __syncthreads();
    const int w    = tid >> 5;
    const int lane = tid & 31;
    float sum = 0.0f;
    #pragma unroll 4
    for (int i = lane; i < DIN; i += 32) sum += krow[i] * Wcb[w * DIN + i];
    #pragma unroll
    for (int o = 16; o > 0; o >>= 1) sum += __shfl_down_sync(0xffffffffu, sum, o);
    if (lane == 0) cb[(size_t)(b * HH + w) * SS + s] = sum;
}

// ---------------------------------------------------------------------------
extern "C" void kernel_launch(void* const* d_in, const int* in_sizes, int n_in,
                              void* d_out, int out_size) {
    const float* queries = (const float*)d_in[0];
    const float* keys    = (const float*)d_in[1];
    const float* values  = (const float*)d_in[2];
    const float* Wq      = (const float*)d_in[4];
    const float* Wk      = (const float*)d_in[5];
    const float* Wv      = (const float*)d_in[6];
    const float* bv      = (const float*)d_in[7];
    const float* Wcb     = (const float*)d_in[8];
    const float* mixing  = (const float*)d_in[9];
    const float* Wd      = (const float*)d_in[10];
    const float* bd      = (const float*)d_in[11];

    float* out = (float*)d_out;

    void *pq, *pk, *pv, *pcb, *pctx, *ppsum, *pprobs;
    cudaGetSymbolAddress(&pq,    g_q);
    cudaGetSymbolAddress(&pk,    g_k);
    cudaGetSymbolAddress(&pv,    g_v);
    cudaGetSymbolAddress(&pcb,   g_cb);
    cudaGetSymbolAddress(&pctx,  g_ctx);
    cudaGetSymbolAddress(&ppsum, g_psum);
    cudaGetSymbolAddress(&pprobs, g_probs);

    float* probs;
    if ((long)out_size >= OUT_ELEMS + PROB_ELEMS) probs = out + OUT_ELEMS;
    else                                           probs = (float*)pprobs;

    const int SC_SMEM  = 3 * 8192 * 4;        // 96 KB
    const int CTX_SMEM = 3 * CTX_STAGE * 4;   // 76.8 KB
    cudaFuncSetAttribute(gemm_cp_kernel<false>,
                         cudaFuncAttributeMaxDynamicSharedMemorySize, SC_SMEM);
    cudaFuncSetAttribute(gemm_cp_kernel<true>,
                         cudaFuncAttributeMaxDynamicSharedMemorySize, SC_SMEM);
    cudaFuncSetAttribute(scores_mma_kernel,
                         cudaFuncAttributeMaxDynamicSharedMemorySize, SC_SMEM);
    cudaFuncSetAttribute(ctx_mma_kernel,
                         cudaFuncAttributeMaxDynamicSharedMemorySize, CTX_SMEM);

    const int M = BB * LL;

    cb_kernel<<<BB * SS, 256>>>(keys, Wcb, (float*)pcb);

    dim3 gproj(DOUT / 128, M / 128);
    gemm_cp_kernel<false><<<gproj, 256, SC_SMEM>>>(queries, Wq, nullptr, (float*)pq, M, DK, DIN);
    gemm_cp_kernel<false><<<gproj, 256, SC_SMEM>>>(keys,    Wk, nullptr, (float*)pk, M, DK, DIN);
    gemm_cp_kernel<true ><<<gproj, 256, SC_SMEM>>>(values,  Wv, bv,      (float*)pv, M, DV, DIN);

    dim3 gsc(SS / 128, LL / 128, BB * HH);
    scores_mma_kernel<<<gsc, 256, SC_SMEM>>>((const float*)pq, (const float*)pk,
                                             mixing, (const float*)pcb,
                                             probs, (float*)ppsum);

    dim3 gctx(LL / 128, BB * HH);
    ctx_mma_kernel<<<gctx, 256, CTX_SMEM>>>(probs, (const float*)ppsum,
                                            (const float*)pv, (float*)pctx);

    gemm_cp_kernel<true><<<gproj, 256, SC_SMEM>>>((const float*)pctx, Wd, bd, out, M, DOUT, DV);
}